// round 8
// baseline (speedup 1.0000x reference)
#include <cuda_runtime.h>
#include <cuda_bf16.h>
#include <cstdint>

// Problem constants (match reference_code)
#define NN 50000
#define EE 800000
#define FIN 256
#define FOUT 64

#define NBLK 49   // ceil(NN / 1024)

// Scratch (no cudaMalloc allowed) — static __device__ globals.
__device__ int   g_cnt[NN];          // in-degree (w/o self loop)
__device__ int   g_fill[NN];         // bucket fill cursor (pre-init to offsets)
__device__ int   g_off[NN + 1];      // CSR offsets
__device__ int   g_bsum[64];         // per-block sums for scan
__device__ int2  g_nbr2[EE];         // CSR: {src node, norm bits} per incoming edge
__device__ float g_deg[NN];          // dinv = rsqrt(deg)
__device__ float g_h[NN * FOUT];     // h = x @ W

// ---------------------------------------------------------------------------
__device__ __forceinline__ uint32_t pk2(float lo, float hi) {
    uint32_t d;
    asm("cvt.rn.bf16x2.f32 %0, %1, %2;" : "=r"(d) : "f"(hi), "f"(lo));
    return d;
}
__device__ __forceinline__ float f_lo16(uint32_t u) { return __uint_as_float(u << 16); }
__device__ __forceinline__ float f_hi16(uint32_t u) { return __uint_as_float(u & 0xffff0000u); }

__device__ __forceinline__ uint32_t smem_u32(const void* p) {
    uint32_t a;
    asm("{ .reg .u64 t; cvta.to.shared.u64 t, %1; cvt.u32.u64 %0, t; }" : "=r"(a) : "l"(p));
    return a;
}

#define LDSM4(r, addr) \
    asm volatile("ldmatrix.sync.aligned.m8n8.x4.shared.b16 {%0,%1,%2,%3}, [%4];" \
        : "=r"((r)[0]), "=r"((r)[1]), "=r"((r)[2]), "=r"((r)[3]) : "r"(addr))

__device__ __forceinline__ void mma_bf16(float* c, const uint32_t* a, uint32_t b0, uint32_t b1) {
    asm volatile(
        "mma.sync.aligned.m16n8k16.row.col.f32.bf16.bf16.f32 "
        "{%0,%1,%2,%3}, {%4,%5,%6,%7}, {%8,%9}, {%0,%1,%2,%3};"
        : "+f"(c[0]), "+f"(c[1]), "+f"(c[2]), "+f"(c[3])
        : "r"(a[0]), "r"(a[1]), "r"(a[2]), "r"(a[3]), "r"(b0), "r"(b1));
}

// ---------------------------------------------------------------------------
// K1: zero counters
__global__ void k_zero() {
    int i = blockIdx.x * blockDim.x + threadIdx.x;
    if (i < NN) g_cnt[i] = 0;
}

// K2: in-degree count over edge dst (4 edges/thread, int4 loads)
__global__ void k_count(const int* __restrict__ dst) {
    int e0 = (blockIdx.x * blockDim.x + threadIdx.x) * 4;
    if (e0 >= EE) return;
    int4 d4 = *reinterpret_cast<const int4*>(dst + e0);
    atomicAdd(&g_cnt[d4.x], 1);
    atomicAdd(&g_cnt[d4.y], 1);
    atomicAdd(&g_cnt[d4.z], 1);
    atomicAdd(&g_cnt[d4.w], 1);
}

// K3a: per-block (1024 elems) sums, coalesced
__global__ __launch_bounds__(1024) void k_scan_a() {
    __shared__ int ws[32];
    const int t = threadIdx.x;
    int idx = blockIdx.x * 1024 + t;
    int v = (idx < NN) ? g_cnt[idx] : 0;
    for (int o = 16; o > 0; o >>= 1) v += __shfl_down_sync(0xffffffffu, v, o);
    if ((t & 31) == 0) ws[t >> 5] = v;
    __syncthreads();
    if (t < 32) {
        int s = ws[t];
        for (int o = 16; o > 0; o >>= 1) s += __shfl_down_sync(0xffffffffu, s, o);
        if (t == 0) g_bsum[blockIdx.x] = s;
    }
}

// K3b: per-block exclusive scan -> g_off, g_fill (cursor), g_deg.
__global__ __launch_bounds__(1024) void k_scan_c() {
    __shared__ int ws[32];
    __shared__ int bpre_s;
    const int t = threadIdx.x;
    const int lane = t & 31;
    const int wid = t >> 5;
    int idx = blockIdx.x * 1024 + t;
    int c = (idx < NN) ? g_cnt[idx] : 0;

    int incl = c;
    for (int o = 1; o < 32; o <<= 1) {
        int u = __shfl_up_sync(0xffffffffu, incl, o);
        if (lane >= o) incl += u;
    }
    if (lane == 31) ws[wid] = incl;

    if (wid == 1) {
        int accp = 0;
        for (int j = lane; j < blockIdx.x; j += 32) accp += g_bsum[j];
        for (int o = 16; o > 0; o >>= 1) accp += __shfl_down_sync(0xffffffffu, accp, o);
        if (lane == 0) bpre_s = accp;
    }
    __syncthreads();
    if (wid == 0) {
        int wv = ws[lane];
        for (int o = 1; o < 32; o <<= 1) {
            int u = __shfl_up_sync(0xffffffffu, wv, o);
            if (lane >= o) wv += u;
        }
        ws[lane] = wv;
    }
    __syncthreads();
    int excl = incl - c + (wid ? ws[wid - 1] : 0);

    if (idx < NN) {
        int off = bpre_s + excl;
        g_off[idx]  = off;
        g_fill[idx] = off;
        g_deg[idx]  = rsqrtf((float)(c + 1));
    }
    if (blockIdx.x == 0 && t == 0) g_off[NN] = EE;
}

// K4: bucket fill — cursor holds offsets; 4 edges/thread; fuse norm compute.
__global__ void k_fill(const int* __restrict__ src, const int* __restrict__ dst) {
    int e0 = (blockIdx.x * blockDim.x + threadIdx.x) * 4;
    if (e0 >= EE) return;
    int4 s4 = *reinterpret_cast<const int4*>(src + e0);
    int4 d4 = *reinterpret_cast<const int4*>(dst + e0);
    float ds0 = g_deg[s4.x], ds1 = g_deg[s4.y], ds2 = g_deg[s4.z], ds3 = g_deg[s4.w];
    float dd0 = g_deg[d4.x], dd1 = g_deg[d4.y], dd2 = g_deg[d4.z], dd3 = g_deg[d4.w];
    int p0 = atomicAdd(&g_fill[d4.x], 1);
    int p1 = atomicAdd(&g_fill[d4.y], 1);
    int p2 = atomicAdd(&g_fill[d4.z], 1);
    int p3 = atomicAdd(&g_fill[d4.w], 1);
    g_nbr2[p0] = make_int2(s4.x, __float_as_int(ds0 * dd0));
    g_nbr2[p1] = make_int2(s4.y, __float_as_int(ds1 * dd1));
    g_nbr2[p2] = make_int2(s4.z, __float_as_int(ds2 * dd2));
    g_nbr2[p3] = make_int2(s4.w, __float_as_int(ds3 * dd3));
}

// ---------------------------------------------------------------------------
// K5: smem-staged split-bf16 GEMM  h = x @ W (see R7 theory).
#define SM_A_HI 0
#define SM_A_LO 16384
#define SM_BF   32768
#define BF_STRIDE 68
#define GEMM_SMEM (SM_BF + 64 * BF_STRIDE * 16)   // 102400 bytes

__global__ __launch_bounds__(512, 2) void k_gemm_mma(
    const float* __restrict__ x, const float* __restrict__ W)
{
    extern __shared__ __align__(16) char sm[];
    uint4* const Bf = reinterpret_cast<uint4*>(sm + SM_BF);
    const uint32_t smbase = smem_u32(sm);

    const int t    = threadIdx.x;
    const int wid  = t >> 5;
    const int lane = t & 31;
    const int g    = lane >> 2;
    const int tig  = lane & 3;
    const int stripe = wid & 7;
    const int nhalf  = wid >> 3;
    const int row0   = blockIdx.x * 128;

    // stage W as pre-packed b-fragments: 4096 frags / 512 thr = 8 each
#pragma unroll
    for (int i = 0; i < 8; ++i) {
        int e = t + i * 512;
        int n = e >> 6, rem = e & 63, s = rem >> 2, tg = rem & 3;
        int kb = s * 16 + tg * 2;
        float w0 = W[kb * FOUT + n];
        float w1 = W[(kb + 1) * FOUT + n];
        float w2 = W[(kb + 8) * FOUT + n];
        float w3 = W[(kb + 9) * FOUT + n];
        uint32_t h01 = pk2(w0, w1);
        uint32_t h23 = pk2(w2, w3);
        uint32_t l01 = pk2(w0 - f_lo16(h01), w1 - f_hi16(h01));
        uint32_t l23 = pk2(w2 - f_lo16(h23), w3 - f_hi16(h23));
        Bf[n * BF_STRIDE + s * 4 + tg] = make_uint4(h01, h23, l01, l23);
    }

    // ldmatrix lane addressing
    const int mat  = lane >> 3;
    const int r8   = lane & 7;
    const int arow = stripe * 16 + (mat & 1) * 8 + r8;
    const int koff = (mat >> 1) * 8;
    const uint32_t xorv   = (uint32_t)((arow & 7) << 4);
    const uint32_t a_hi_b = smbase + SM_A_HI + arow * 128;
    const uint32_t a_lo_b = smbase + SM_A_LO + arow * 128;

    float acc[4][4];
#pragma unroll
    for (int i = 0; i < 4; ++i)
#pragma unroll
        for (int j = 0; j < 4; ++j) acc[i][j] = 0.0f;

#pragma unroll 1
    for (int c = 0; c < 4; ++c) {
        __syncthreads();

        // load A chunk 128x64 fp32 coalesced, convert, store swizzled
#pragma unroll
        for (int i = 0; i < 4; ++i) {
            int idx = t + i * 512;
            int r = idx >> 4, q = idx & 15;
            int grow = row0 + r;
            float4 v = make_float4(0.f, 0.f, 0.f, 0.f);
            if (grow < NN)
                v = *reinterpret_cast<const float4*>(x + (size_t)grow * FIN + c * 64 + q * 4);
            uint32_t h0 = pk2(v.x, v.y), h1 = pk2(v.z, v.w);
            uint32_t l0 = pk2(v.x - f_lo16(h0), v.y - f_hi16(h0));
            uint32_t l1 = pk2(v.z - f_lo16(h1), v.w - f_hi16(h1));
            uint32_t boff = (uint32_t)(r * 128) + (((uint32_t)(q * 8)) ^ ((uint32_t)(r & 7) << 4));
            *reinterpret_cast<uint2*>(sm + SM_A_HI + boff) = make_uint2(h0, h1);
            *reinterpret_cast<uint2*>(sm + SM_A_LO + boff) = make_uint2(l0, l1);
        }
        __syncthreads();

#pragma unroll
        for (int ks = 0; ks < 4; ++ks) {
            uint32_t kb = ((uint32_t)((ks * 16 + koff) * 2)) ^ xorv;
            uint32_t ah[4], al[4];
            LDSM4(ah, a_hi_b + kb);
            LDSM4(al, a_lo_b + kb);
            const int s = c * 4 + ks;
#pragma unroll
            for (int nt = 0; nt < 4; ++nt) {
                uint4 f = Bf[(nhalf * 32 + nt * 8 + g) * BF_STRIDE + s * 4 + tig];
                mma_bf16(acc[nt], ah, f.x, f.y);
                mma_bf16(acc[nt], ah, f.z, f.w);
                mma_bf16(acc[nt], al, f.x, f.y);
            }
        }
    }

    const int row1 = row0 + stripe * 16 + g;
    const int row2 = row1 + 8;
#pragma unroll
    for (int nt = 0; nt < 4; ++nt) {
        int c0 = nhalf * 32 + nt * 8 + tig * 2;
        if (row1 < NN)
            *reinterpret_cast<float2*>(&g_h[(size_t)row1 * FOUT + c0]) =
                make_float2(acc[nt][0], acc[nt][1]);
        if (row2 < NN)
            *reinterpret_cast<float2*>(&g_h[(size_t)row2 * FOUT + c0]) =
                make_float2(acc[nt][2], acc[nt][3]);
    }
}

// ---------------------------------------------------------------------------
// K6: CSR gather. 2 nodes/warp, norm pre-fused, x4 unroll (proven R6 form).
__global__ __launch_bounds__(256) void k_gather(
    const float* __restrict__ bias, float* __restrict__ out)
{
    const int warp = blockIdx.x * 8 + (threadIdx.x >> 5);
    const int lane = threadIdx.x & 31;
    const int half = lane >> 4;
    const int hl   = lane & 15;
    const int node = warp * 2 + half;
    if (node >= NN) return;

    const float dinv = g_deg[node];
    const int beg = g_off[node];
    const int end = g_off[node + 1];

    float4 a = *reinterpret_cast<const float4*>(&g_h[(size_t)node * FOUT + hl * 4]);
    const float sl = dinv * dinv;
    a.x *= sl; a.y *= sl; a.z *= sl; a.w *= sl;

    int j = beg;
    for (; j + 4 <= end; j += 4) {
        int2 e0 = g_nbr2[j];
        int2 e1 = g_nbr2[j + 1];
        int2 e2 = g_nbr2[j + 2];
        int2 e3 = g_nbr2[j + 3];
        float4 v0 = *reinterpret_cast<const float4*>(&g_h[(size_t)e0.x * FOUT + hl * 4]);
        float4 v1 = *reinterpret_cast<const float4*>(&g_h[(size_t)e1.x * FOUT + hl * 4]);
        float4 v2 = *reinterpret_cast<const float4*>(&g_h[(size_t)e2.x * FOUT + hl * 4]);
        float4 v3 = *reinterpret_cast<const float4*>(&g_h[(size_t)e3.x * FOUT + hl * 4]);
        float n0 = __int_as_float(e0.y), n1 = __int_as_float(e1.y);
        float n2 = __int_as_float(e2.y), n3 = __int_as_float(e3.y);
        a.x = fmaf(v0.x, n0, a.x); a.y = fmaf(v0.y, n0, a.y);
        a.z = fmaf(v0.z, n0, a.z); a.w = fmaf(v0.w, n0, a.w);
        a.x = fmaf(v1.x, n1, a.x); a.y = fmaf(v1.y, n1, a.y);
        a.z = fmaf(v1.z, n1, a.z); a.w = fmaf(v1.w, n1, a.w);
        a.x = fmaf(v2.x, n2, a.x); a.y = fmaf(v2.y, n2, a.y);
        a.z = fmaf(v2.z, n2, a.z); a.w = fmaf(v2.w, n2, a.w);
        a.x = fmaf(v3.x, n3, a.x); a.y = fmaf(v3.y, n3, a.y);
        a.z = fmaf(v3.z, n3, a.z); a.w = fmaf(v3.w, n3, a.w);
    }
    for (; j < end; ++j) {
        int2 e0 = g_nbr2[j];
        float n0 = __int_as_float(e0.y);
        float4 v0 = *reinterpret_cast<const float4*>(&g_h[(size_t)e0.x * FOUT + hl * 4]);
        a.x = fmaf(v0.x, n0, a.x); a.y = fmaf(v0.y, n0, a.y);
        a.z = fmaf(v0.z, n0, a.z); a.w = fmaf(v0.w, n0, a.w);
    }

    float4 bb = *reinterpret_cast<const float4*>(bias + hl * 4);
    a.x = fmaxf(a.x + bb.x, 0.f);
    a.y = fmaxf(a.y + bb.y, 0.f);
    a.z = fmaxf(a.z + bb.z, 0.f);
    a.w = fmaxf(a.w + bb.w, 0.f);
    *reinterpret_cast<float4*>(&out[(size_t)node * FOUT + hl * 4]) = a;
}

// ---------------------------------------------------------------------------
extern "C" void kernel_launch(void* const* d_in, const int* in_sizes, int n_in,
                              void* d_out, int out_size)
{
    const float* x   = (const float*)d_in[0];   // [N, 256]
    const int*   adj = (const int*)d_in[1];     // [2, E]
    const float* W   = (const float*)d_in[2];   // [256, 64]
    const float* b   = (const float*)d_in[3];   // [64]
    float*       out = (float*)d_out;           // [N, 64]

    const int* src = adj;
    const int* dst = adj + EE;

    static bool attr_set = false;
    if (!attr_set) {
        cudaFuncSetAttribute(k_gemm_mma,
                             cudaFuncAttributeMaxDynamicSharedMemorySize, GEMM_SMEM);
        attr_set = true;
    }

    // CSR build; GEMM is independent and placed 4th so ncu profiles it.
    k_zero<<<(NN + 255) / 256, 256>>>();
    k_count<<<(EE / 4 + 255) / 256, 256>>>(dst);
    k_scan_a<<<NBLK, 1024>>>();
    k_gemm_mma<<<(NN + 127) / 128, 512, GEMM_SMEM>>>(x, W);   // 4th launch
    k_scan_c<<<NBLK, 1024>>>();
    k_fill<<<(EE / 4 + 255) / 256, 256>>>(src, dst);

    // fused gather + self loop + bias + relu
    k_gather<<<(NN / 2 + 7) / 8, 256>>>(b, out);
}

// round 9
// speedup vs baseline: 1.0027x; 1.0027x over previous
#include <cuda_runtime.h>
#include <cuda_bf16.h>
#include <cstdint>

// Problem constants (match reference_code)
#define NN 50000
#define EE 800000
#define FIN 256
#define FOUT 64

#define NBLK 49   // ceil(NN / 1024)

// Scratch (no cudaMalloc allowed) — static __device__ globals.
__device__ int   g_cnt[NN];          // in-degree (w/o self loop)
__device__ int   g_fill[NN];         // bucket fill cursor (pre-init to offsets)
__device__ int   g_off[NN + 1];      // CSR offsets
__device__ int   g_bsum[64];         // per-block sums for scan
__device__ int2  g_nbr2[EE];         // CSR: {src node, norm bits} per incoming edge
__device__ float g_deg[NN];          // dinv = rsqrt(deg)
__device__ float g_h[NN * FOUT];     // h = x @ W

// ---------------------------------------------------------------------------
__device__ __forceinline__ uint32_t pk2(float lo, float hi) {
    uint32_t d;
    asm("cvt.rn.bf16x2.f32 %0, %1, %2;" : "=r"(d) : "f"(hi), "f"(lo));
    return d;
}
__device__ __forceinline__ float f_lo16(uint32_t u) { return __uint_as_float(u << 16); }
__device__ __forceinline__ float f_hi16(uint32_t u) { return __uint_as_float(u & 0xffff0000u); }

__device__ __forceinline__ uint32_t smem_u32(const void* p) {
    uint32_t a;
    asm("{ .reg .u64 t; cvta.to.shared.u64 t, %1; cvt.u32.u64 %0, t; }" : "=r"(a) : "l"(p));
    return a;
}

#define LDSM4(r, addr) \
    asm volatile("ldmatrix.sync.aligned.m8n8.x4.shared.b16 {%0,%1,%2,%3}, [%4];" \
        : "=r"((r)[0]), "=r"((r)[1]), "=r"((r)[2]), "=r"((r)[3]) : "r"(addr))

__device__ __forceinline__ void mma_bf16(float* c, const uint32_t* a, uint32_t b0, uint32_t b1) {
    asm volatile(
        "mma.sync.aligned.m16n8k16.row.col.f32.bf16.bf16.f32 "
        "{%0,%1,%2,%3}, {%4,%5,%6,%7}, {%8,%9}, {%0,%1,%2,%3};"
        : "+f"(c[0]), "+f"(c[1]), "+f"(c[2]), "+f"(c[3])
        : "r"(a[0]), "r"(a[1]), "r"(a[2]), "r"(a[3]), "r"(b0), "r"(b1));
}

// ---------------------------------------------------------------------------
// K1: zero counters
__global__ void k_zero() {
    int i = blockIdx.x * blockDim.x + threadIdx.x;
    if (i < NN) g_cnt[i] = 0;
}

// K2: in-degree count over edge dst (4 edges/thread, int4 loads)
__global__ void k_count(const int* __restrict__ dst) {
    int e0 = (blockIdx.x * blockDim.x + threadIdx.x) * 4;
    if (e0 >= EE) return;
    int4 d4 = *reinterpret_cast<const int4*>(dst + e0);
    atomicAdd(&g_cnt[d4.x], 1);
    atomicAdd(&g_cnt[d4.y], 1);
    atomicAdd(&g_cnt[d4.z], 1);
    atomicAdd(&g_cnt[d4.w], 1);
}

// K3a: per-block (1024 elems) sums, coalesced
__global__ __launch_bounds__(1024) void k_scan_a() {
    __shared__ int ws[32];
    const int t = threadIdx.x;
    int idx = blockIdx.x * 1024 + t;
    int v = (idx < NN) ? g_cnt[idx] : 0;
    for (int o = 16; o > 0; o >>= 1) v += __shfl_down_sync(0xffffffffu, v, o);
    if ((t & 31) == 0) ws[t >> 5] = v;
    __syncthreads();
    if (t < 32) {
        int s = ws[t];
        for (int o = 16; o > 0; o >>= 1) s += __shfl_down_sync(0xffffffffu, s, o);
        if (t == 0) g_bsum[blockIdx.x] = s;
    }
}

// K3b: per-block exclusive scan -> g_off, g_fill (cursor), g_deg.
__global__ __launch_bounds__(1024) void k_scan_c() {
    __shared__ int ws[32];
    __shared__ int bpre_s;
    const int t = threadIdx.x;
    const int lane = t & 31;
    const int wid = t >> 5;
    int idx = blockIdx.x * 1024 + t;
    int c = (idx < NN) ? g_cnt[idx] : 0;

    int incl = c;
    for (int o = 1; o < 32; o <<= 1) {
        int u = __shfl_up_sync(0xffffffffu, incl, o);
        if (lane >= o) incl += u;
    }
    if (lane == 31) ws[wid] = incl;

    if (wid == 1) {
        int accp = 0;
        for (int j = lane; j < blockIdx.x; j += 32) accp += g_bsum[j];
        for (int o = 16; o > 0; o >>= 1) accp += __shfl_down_sync(0xffffffffu, accp, o);
        if (lane == 0) bpre_s = accp;
    }
    __syncthreads();
    if (wid == 0) {
        int wv = ws[lane];
        for (int o = 1; o < 32; o <<= 1) {
            int u = __shfl_up_sync(0xffffffffu, wv, o);
            if (lane >= o) wv += u;
        }
        ws[lane] = wv;
    }
    __syncthreads();
    int excl = incl - c + (wid ? ws[wid - 1] : 0);

    if (idx < NN) {
        int off = bpre_s + excl;
        g_off[idx]  = off;
        g_fill[idx] = off;
        g_deg[idx]  = rsqrtf((float)(c + 1));
    }
    if (blockIdx.x == 0 && t == 0) g_off[NN] = EE;
}

// K4: bucket fill — cursor holds offsets; 4 edges/thread; fuse norm compute.
__global__ void k_fill(const int* __restrict__ src, const int* __restrict__ dst) {
    int e0 = (blockIdx.x * blockDim.x + threadIdx.x) * 4;
    if (e0 >= EE) return;
    int4 s4 = *reinterpret_cast<const int4*>(src + e0);
    int4 d4 = *reinterpret_cast<const int4*>(dst + e0);
    float ds0 = g_deg[s4.x], ds1 = g_deg[s4.y], ds2 = g_deg[s4.z], ds3 = g_deg[s4.w];
    float dd0 = g_deg[d4.x], dd1 = g_deg[d4.y], dd2 = g_deg[d4.z], dd3 = g_deg[d4.w];
    int p0 = atomicAdd(&g_fill[d4.x], 1);
    int p1 = atomicAdd(&g_fill[d4.y], 1);
    int p2 = atomicAdd(&g_fill[d4.z], 1);
    int p3 = atomicAdd(&g_fill[d4.w], 1);
    g_nbr2[p0] = make_int2(s4.x, __float_as_int(ds0 * dd0));
    g_nbr2[p1] = make_int2(s4.y, __float_as_int(ds1 * dd1));
    g_nbr2[p2] = make_int2(s4.z, __float_as_int(ds2 * dd2));
    g_nbr2[p3] = make_int2(s4.w, __float_as_int(ds3 * dd3));
}

// ---------------------------------------------------------------------------
// K5: smem-staged split-bf16 GEMM  h = x @ W.
// FULL K=256 staged at once: one coalesced load phase (16 float4/thread,
// huge MLP), ONE syncthreads, then pure ldmatrix+MMA compute. 196KB smem,
// 1 CTA/SM. A layout: 4 chunk-buffers of 16KB each (row stride 128B,
// SW128-swizzled) — addressing identical to the verified chunked version.
#define SM_A_HI 0
#define SM_A_LO 65536
#define SM_BF   131072
#define BF_STRIDE 68
#define GEMM_SMEM (SM_BF + 64 * BF_STRIDE * 16)   // 131072 + 69632 = 200704

__global__ __launch_bounds__(512, 1) void k_gemm_mma(
    const float* __restrict__ x, const float* __restrict__ W)
{
    extern __shared__ __align__(16) char sm[];
    uint4* const Bf = reinterpret_cast<uint4*>(sm + SM_BF);
    const uint32_t smbase = smem_u32(sm);

    const int t    = threadIdx.x;
    const int wid  = t >> 5;
    const int lane = t & 31;
    const int g    = lane >> 2;
    const int tig  = lane & 3;
    const int stripe = wid & 7;
    const int nhalf  = wid >> 3;
    const int row0   = blockIdx.x * 128;

    // stage W as pre-packed b-fragments: 4096 frags / 512 thr = 8 each
#pragma unroll
    for (int i = 0; i < 8; ++i) {
        int e = t + i * 512;
        int n = e >> 6, rem = e & 63, s = rem >> 2, tg = rem & 3;
        int kb = s * 16 + tg * 2;
        float w0 = W[kb * FOUT + n];
        float w1 = W[(kb + 1) * FOUT + n];
        float w2 = W[(kb + 8) * FOUT + n];
        float w3 = W[(kb + 9) * FOUT + n];
        uint32_t h01 = pk2(w0, w1);
        uint32_t h23 = pk2(w2, w3);
        uint32_t l01 = pk2(w0 - f_lo16(h01), w1 - f_hi16(h01));
        uint32_t l23 = pk2(w2 - f_lo16(h23), w3 - f_hi16(h23));
        Bf[n * BF_STRIDE + s * 4 + tg] = make_uint4(h01, h23, l01, l23);
    }

    // ---- load ALL of A (128 rows x 256 cols): 8192 float4 / 512 thr = 16 ----
    // warp reads 512B contiguous per iteration -> fully coalesced.
#pragma unroll
    for (int i = 0; i < 16; ++i) {
        int idx = t + i * 512;
        int r = idx >> 6;            // row 0..127
        int q = idx & 63;            // float4 col 0..63 (k = q*4)
        int grow = row0 + r;
        float4 v = make_float4(0.f, 0.f, 0.f, 0.f);
        if (grow < NN)
            v = *reinterpret_cast<const float4*>(x + (size_t)grow * FIN + q * 4);
        uint32_t h0 = pk2(v.x, v.y), h1 = pk2(v.z, v.w);
        uint32_t l0 = pk2(v.x - f_lo16(h0), v.y - f_hi16(h0));
        uint32_t l1 = pk2(v.z - f_lo16(h1), v.w - f_hi16(h1));
        int chunk = q >> 4;          // 64-col chunk 0..3
        int qq = q & 15;             // quad within chunk
        uint32_t boff = (uint32_t)(chunk * 16384) + (uint32_t)(r * 128)
                      + (((uint32_t)(qq * 8)) ^ ((uint32_t)(r & 7) << 4));
        *reinterpret_cast<uint2*>(sm + SM_A_HI + boff) = make_uint2(h0, h1);
        *reinterpret_cast<uint2*>(sm + SM_A_LO + boff) = make_uint2(l0, l1);
    }
    __syncthreads();

    // ldmatrix lane addressing
    const int mat  = lane >> 3;
    const int r8   = lane & 7;
    const int arow = stripe * 16 + (mat & 1) * 8 + r8;
    const int koff = (mat >> 1) * 8;
    const uint32_t xorv   = (uint32_t)((arow & 7) << 4);
    const uint32_t a_hi_b = smbase + SM_A_HI + arow * 128;
    const uint32_t a_lo_b = smbase + SM_A_LO + arow * 128;

    float acc[4][4];
#pragma unroll
    for (int i = 0; i < 4; ++i)
#pragma unroll
        for (int j = 0; j < 4; ++j) acc[i][j] = 0.0f;

#pragma unroll
    for (int c = 0; c < 4; ++c) {
        const uint32_t cbase = (uint32_t)(c * 16384);
#pragma unroll
        for (int ks = 0; ks < 4; ++ks) {
            uint32_t kb = cbase + (((uint32_t)((ks * 16 + koff) * 2)) ^ xorv);
            uint32_t ah[4], al[4];
            LDSM4(ah, a_hi_b + kb);
            LDSM4(al, a_lo_b + kb);
            const int s = c * 4 + ks;
#pragma unroll
            for (int nt = 0; nt < 4; ++nt) {
                uint4 f = Bf[(nhalf * 32 + nt * 8 + g) * BF_STRIDE + s * 4 + tig];
                mma_bf16(acc[nt], ah, f.x, f.y);
                mma_bf16(acc[nt], ah, f.z, f.w);
                mma_bf16(acc[nt], al, f.x, f.y);
            }
        }
    }

    const int row1 = row0 + stripe * 16 + g;
    const int row2 = row1 + 8;
#pragma unroll
    for (int nt = 0; nt < 4; ++nt) {
        int c0 = nhalf * 32 + nt * 8 + tig * 2;
        if (row1 < NN)
            *reinterpret_cast<float2*>(&g_h[(size_t)row1 * FOUT + c0]) =
                make_float2(acc[nt][0], acc[nt][1]);
        if (row2 < NN)
            *reinterpret_cast<float2*>(&g_h[(size_t)row2 * FOUT + c0]) =
                make_float2(acc[nt][2], acc[nt][3]);
    }
}

// ---------------------------------------------------------------------------
// K6: CSR gather. 2 nodes/warp, norm pre-fused, x4 unroll (proven form).
__global__ __launch_bounds__(256) void k_gather(
    const float* __restrict__ bias, float* __restrict__ out)
{
    const int warp = blockIdx.x * 8 + (threadIdx.x >> 5);
    const int lane = threadIdx.x & 31;
    const int half = lane >> 4;
    const int hl   = lane & 15;
    const int node = warp * 2 + half;
    if (node >= NN) return;

    const float dinv = g_deg[node];
    const int beg = g_off[node];
    const int end = g_off[node + 1];

    float4 a = *reinterpret_cast<const float4*>(&g_h[(size_t)node * FOUT + hl * 4]);
    const float sl = dinv * dinv;
    a.x *= sl; a.y *= sl; a.z *= sl; a.w *= sl;

    int j = beg;
    for (; j + 4 <= end; j += 4) {
        int2 e0 = g_nbr2[j];
        int2 e1 = g_nbr2[j + 1];
        int2 e2 = g_nbr2[j + 2];
        int2 e3 = g_nbr2[j + 3];
        float4 v0 = *reinterpret_cast<const float4*>(&g_h[(size_t)e0.x * FOUT + hl * 4]);
        float4 v1 = *reinterpret_cast<const float4*>(&g_h[(size_t)e1.x * FOUT + hl * 4]);
        float4 v2 = *reinterpret_cast<const float4*>(&g_h[(size_t)e2.x * FOUT + hl * 4]);
        float4 v3 = *reinterpret_cast<const float4*>(&g_h[(size_t)e3.x * FOUT + hl * 4]);
        float n0 = __int_as_float(e0.y), n1 = __int_as_float(e1.y);
        float n2 = __int_as_float(e2.y), n3 = __int_as_float(e3.y);
        a.x = fmaf(v0.x, n0, a.x); a.y = fmaf(v0.y, n0, a.y);
        a.z = fmaf(v0.z, n0, a.z); a.w = fmaf(v0.w, n0, a.w);
        a.x = fmaf(v1.x, n1, a.x); a.y = fmaf(v1.y, n1, a.y);
        a.z = fmaf(v1.z, n1, a.z); a.w = fmaf(v1.w, n1, a.w);
        a.x = fmaf(v2.x, n2, a.x); a.y = fmaf(v2.y, n2, a.y);
        a.z = fmaf(v2.z, n2, a.z); a.w = fmaf(v2.w, n2, a.w);
        a.x = fmaf(v3.x, n3, a.x); a.y = fmaf(v3.y, n3, a.y);
        a.z = fmaf(v3.z, n3, a.z); a.w = fmaf(v3.w, n3, a.w);
    }
    for (; j < end; ++j) {
        int2 e0 = g_nbr2[j];
        float n0 = __int_as_float(e0.y);
        float4 v0 = *reinterpret_cast<const float4*>(&g_h[(size_t)e0.x * FOUT + hl * 4]);
        a.x = fmaf(v0.x, n0, a.x); a.y = fmaf(v0.y, n0, a.y);
        a.z = fmaf(v0.z, n0, a.z); a.w = fmaf(v0.w, n0, a.w);
    }

    float4 bb = *reinterpret_cast<const float4*>(bias + hl * 4);
    a.x = fmaxf(a.x + bb.x, 0.f);
    a.y = fmaxf(a.y + bb.y, 0.f);
    a.z = fmaxf(a.z + bb.z, 0.f);
    a.w = fmaxf(a.w + bb.w, 0.f);
    *reinterpret_cast<float4*>(&out[(size_t)node * FOUT + hl * 4]) = a;
}

// ---------------------------------------------------------------------------
extern "C" void kernel_launch(void* const* d_in, const int* in_sizes, int n_in,
                              void* d_out, int out_size)
{
    const float* x   = (const float*)d_in[0];   // [N, 256]
    const int*   adj = (const int*)d_in[1];     // [2, E]
    const float* W   = (const float*)d_in[2];   // [256, 64]
    const float* b   = (const float*)d_in[3];   // [64]
    float*       out = (float*)d_out;           // [N, 64]

    const int* src = adj;
    const int* dst = adj + EE;

    static bool attr_set = false;
    if (!attr_set) {
        cudaFuncSetAttribute(k_gemm_mma,
                             cudaFuncAttributeMaxDynamicSharedMemorySize, GEMM_SMEM);
        attr_set = true;
    }

    // CSR build; GEMM is independent and placed 4th so ncu profiles it.
    k_zero<<<(NN + 255) / 256, 256>>>();
    k_count<<<(EE / 4 + 255) / 256, 256>>>(dst);
    k_scan_a<<<NBLK, 1024>>>();
    k_gemm_mma<<<(NN + 127) / 128, 512, GEMM_SMEM>>>(x, W);   // 4th launch
    k_scan_c<<<NBLK, 1024>>>();
    k_fill<<<(EE / 4 + 255) / 256, 256>>>(src, dst);

    // fused gather + self loop + bias + relu
    k_gather<<<(NN / 2 + 7) / 8, 256>>>(b, out);
}

// round 10
// speedup vs baseline: 1.2678x; 1.2643x over previous
#include <cuda_runtime.h>
#include <cuda_bf16.h>
#include <cstdint>

// Problem constants (match reference_code)
#define NN 50000
#define EE 800000
#define FIN 256
#define FOUT 64

#define NBLK 49   // ceil(NN / 1024)

// Scratch (no cudaMalloc allowed) — static __device__ globals.
__device__ int   g_cnt[NN];          // in-degree (w/o self loop)
__device__ int   g_fill[NN];         // bucket fill cursor (pre-init to offsets)
__device__ int   g_off[NN + 1];      // CSR offsets
__device__ int   g_bsum[64];         // per-block sums for scan
__device__ int   g_nbr[EE];          // CSR: src node per incoming edge (4B/edge)
__device__ float g_deg[NN];          // dinv = rsqrt(deg)
__device__ float g_h[NN * FOUT];     // h = x @ W

// ---------------------------------------------------------------------------
__device__ __forceinline__ uint32_t pk2(float lo, float hi) {
    uint32_t d;
    asm("cvt.rn.bf16x2.f32 %0, %1, %2;" : "=r"(d) : "f"(hi), "f"(lo));
    return d;
}
__device__ __forceinline__ float f_lo16(uint32_t u) { return __uint_as_float(u << 16); }
__device__ __forceinline__ float f_hi16(uint32_t u) { return __uint_as_float(u & 0xffff0000u); }

__device__ __forceinline__ void mma_bf16(float* c, const uint32_t* a, uint32_t b0, uint32_t b1) {
    asm volatile(
        "mma.sync.aligned.m16n8k16.row.col.f32.bf16.bf16.f32 "
        "{%0,%1,%2,%3}, {%4,%5,%6,%7}, {%8,%9}, {%0,%1,%2,%3};"
        : "+f"(c[0]), "+f"(c[1]), "+f"(c[2]), "+f"(c[3])
        : "r"(a[0]), "r"(a[1]), "r"(a[2]), "r"(a[3]), "r"(b0), "r"(b1));
}

// ---------------------------------------------------------------------------
// K1: zero counters
__global__ void k_zero() {
    int i = blockIdx.x * blockDim.x + threadIdx.x;
    if (i < NN) g_cnt[i] = 0;
}

// K2: in-degree count over edge dst (4 edges/thread, int4 loads)
__global__ void k_count(const int* __restrict__ dst) {
    int e0 = (blockIdx.x * blockDim.x + threadIdx.x) * 4;
    if (e0 >= EE) return;
    int4 d4 = *reinterpret_cast<const int4*>(dst + e0);
    atomicAdd(&g_cnt[d4.x], 1);
    atomicAdd(&g_cnt[d4.y], 1);
    atomicAdd(&g_cnt[d4.z], 1);
    atomicAdd(&g_cnt[d4.w], 1);
}

// K3a: per-block (1024 elems) sums, coalesced
__global__ __launch_bounds__(1024) void k_scan_a() {
    __shared__ int ws[32];
    const int t = threadIdx.x;
    int idx = blockIdx.x * 1024 + t;
    int v = (idx < NN) ? g_cnt[idx] : 0;
    for (int o = 16; o > 0; o >>= 1) v += __shfl_down_sync(0xffffffffu, v, o);
    if ((t & 31) == 0) ws[t >> 5] = v;
    __syncthreads();
    if (t < 32) {
        int s = ws[t];
        for (int o = 16; o > 0; o >>= 1) s += __shfl_down_sync(0xffffffffu, s, o);
        if (t == 0) g_bsum[blockIdx.x] = s;
    }
}

// K3b: per-block exclusive scan -> g_off, g_fill (cursor), g_deg.
// Each block computes its own global prefix from g_bsum (warp 1).
__global__ __launch_bounds__(1024) void k_scan_c() {
    __shared__ int ws[32];
    __shared__ int bpre_s;
    const int t = threadIdx.x;
    const int lane = t & 31;
    const int wid = t >> 5;
    int idx = blockIdx.x * 1024 + t;
    int c = (idx < NN) ? g_cnt[idx] : 0;

    int incl = c;
    for (int o = 1; o < 32; o <<= 1) {
        int u = __shfl_up_sync(0xffffffffu, incl, o);
        if (lane >= o) incl += u;
    }
    if (lane == 31) ws[wid] = incl;

    if (wid == 1) {
        int accp = 0;
        for (int j = lane; j < blockIdx.x; j += 32) accp += g_bsum[j];
        for (int o = 16; o > 0; o >>= 1) accp += __shfl_down_sync(0xffffffffu, accp, o);
        if (lane == 0) bpre_s = accp;
    }
    __syncthreads();
    if (wid == 0) {
        int wv = ws[lane];
        for (int o = 1; o < 32; o <<= 1) {
            int u = __shfl_up_sync(0xffffffffu, wv, o);
            if (lane >= o) wv += u;
        }
        ws[lane] = wv;
    }
    __syncthreads();
    int excl = incl - c + (wid ? ws[wid - 1] : 0);

    if (idx < NN) {
        int off = bpre_s + excl;
        g_off[idx]  = off;
        g_fill[idx] = off;
        g_deg[idx]  = rsqrtf((float)(c + 1));
    }
    if (blockIdx.x == 0 && t == 0) g_off[NN] = EE;
}

// K4: bucket fill — cursor holds offsets; 4 edges/thread; 4B/edge store.
__global__ void k_fill(const int* __restrict__ src, const int* __restrict__ dst) {
    int e0 = (blockIdx.x * blockDim.x + threadIdx.x) * 4;
    if (e0 >= EE) return;
    int4 s4 = *reinterpret_cast<const int4*>(src + e0);
    int4 d4 = *reinterpret_cast<const int4*>(dst + e0);
    int p0 = atomicAdd(&g_fill[d4.x], 1);
    int p1 = atomicAdd(&g_fill[d4.y], 1);
    int p2 = atomicAdd(&g_fill[d4.z], 1);
    int p3 = atomicAdd(&g_fill[d4.w], 1);
    g_nbr[p0] = s4.x;
    g_nbr[p1] = s4.y;
    g_nbr[p2] = s4.z;
    g_nbr[p3] = s4.w;
}

// ---------------------------------------------------------------------------
// K5: mma.sync bf16 GEMM  h = x @ W  with split-bf16 — the measured-best
// 40.0µs version (R7): 512 thr, 16 warps = 8 m-stripes x 2 n-halves,
// acc[4][4], direct-LDG A fragments, smem bf16 hi/lo W, pk2 conversions.

#define PAD_K 264   // 256 + 8 pad: conflict-free b-frag LDS
#define B_HI_OFF 0
#define B_LO_OFF (64 * PAD_K)               // in ushort units
#define GEMM_SMEM (2 * 64 * PAD_K * 2)      // bytes = 67584

__global__ __launch_bounds__(512, 2) void k_gemm_mma(
    const float* __restrict__ x, const float* __restrict__ W)
{
    extern __shared__ __align__(16) ushort Bs[];   // [2][64][PAD_K] bf16 bits

    const int t    = threadIdx.x;
    const int wid  = t >> 5;
    const int lane = t & 31;
    const int g    = lane >> 2;
    const int tig  = lane & 3;

    // ---- stage W -> smem bf16 hi/lo, [n][k] layout ----
#pragma unroll 8
    for (int it = 0; it < 32; ++it) {
        int idx = t + it * 512;
        int k = idx >> 6;
        int n = idx & 63;
        float w = W[k * FOUT + n];
        uint32_t hp = pk2(w, 0.f);
        Bs[B_HI_OFF + n * PAD_K + k] = (ushort)(hp & 0xffffu);
        Bs[B_LO_OFF + n * PAD_K + k] =
            (ushort)(pk2(w - f_lo16(hp), 0.f) & 0xffffu);
    }
    __syncthreads();

    // ---- warp tiling ----
    const int stripe = wid & 7;
    const int nhalf  = wid >> 3;
    const int row0   = blockIdx.x * 128 + stripe * 16;

    const int row1 = row0 + g;
    const int row2 = row1 + 8;
    const bool v1 = (row1 < NN);
    const bool v2 = (row2 < NN);
    const float* xr1 = x + (size_t)row1 * FIN;
    const float* xr2 = x + (size_t)row2 * FIN;

    float acc[4][4];
#pragma unroll
    for (int i = 0; i < 4; ++i)
#pragma unroll
        for (int j = 0; j < 4; ++j) acc[i][j] = 0.0f;

#pragma unroll 4
    for (int s = 0; s < 16; ++s) {
        const int kb = s * 16 + tig * 2;

        float2 p0 = v1 ? *reinterpret_cast<const float2*>(xr1 + kb)     : make_float2(0.f, 0.f);
        float2 p1 = v2 ? *reinterpret_cast<const float2*>(xr2 + kb)     : make_float2(0.f, 0.f);
        float2 p2 = v1 ? *reinterpret_cast<const float2*>(xr1 + kb + 8) : make_float2(0.f, 0.f);
        float2 p3 = v2 ? *reinterpret_cast<const float2*>(xr2 + kb + 8) : make_float2(0.f, 0.f);

        uint32_t a_hi[4], a_lo[4];
        a_hi[0] = pk2(p0.x, p0.y); a_lo[0] = pk2(p0.x - f_lo16(a_hi[0]), p0.y - f_hi16(a_hi[0]));
        a_hi[1] = pk2(p1.x, p1.y); a_lo[1] = pk2(p1.x - f_lo16(a_hi[1]), p1.y - f_hi16(a_hi[1]));
        a_hi[2] = pk2(p2.x, p2.y); a_lo[2] = pk2(p2.x - f_lo16(a_hi[2]), p2.y - f_hi16(a_hi[2]));
        a_hi[3] = pk2(p3.x, p3.y); a_lo[3] = pk2(p3.x - f_lo16(a_hi[3]), p3.y - f_hi16(a_hi[3]));

#pragma unroll
        for (int nt = 0; nt < 4; ++nt) {
            int n = nhalf * 32 + nt * 8 + g;
            const ushort* bh = &Bs[B_HI_OFF + n * PAD_K + kb];
            const ushort* bl = &Bs[B_LO_OFF + n * PAD_K + kb];
            uint32_t bh0 = *reinterpret_cast<const uint32_t*>(bh);
            uint32_t bh1 = *reinterpret_cast<const uint32_t*>(bh + 8);
            uint32_t bl0 = *reinterpret_cast<const uint32_t*>(bl);
            uint32_t bl1 = *reinterpret_cast<const uint32_t*>(bl + 8);
            mma_bf16(acc[nt], a_hi, bh0, bh1);
            mma_bf16(acc[nt], a_hi, bl0, bl1);
            mma_bf16(acc[nt], a_lo, bh0, bh1);
        }
    }

    // ---- epilogue: write h ----
#pragma unroll
    for (int nt = 0; nt < 4; ++nt) {
        int c0 = nhalf * 32 + nt * 8 + tig * 2;
        if (v1)
            *reinterpret_cast<float2*>(&g_h[(size_t)row1 * FOUT + c0]) =
                make_float2(acc[nt][0], acc[nt][1]);
        if (v2)
            *reinterpret_cast<float2*>(&g_h[(size_t)row2 * FOUT + c0]) =
                make_float2(acc[nt][2], acc[nt][3]);
    }
}

// ---------------------------------------------------------------------------
// K6: CSR gather. 2 nodes/warp (16 lanes x float4), 4B/edge, deg loads
// in-loop (L2 broadcast), x4 unroll — the 86.9µs config's aggregation path.
__global__ __launch_bounds__(256) void k_gather(
    const float* __restrict__ bias, float* __restrict__ out)
{
    const int warp = blockIdx.x * 8 + (threadIdx.x >> 5);
    const int lane = threadIdx.x & 31;
    const int half = lane >> 4;
    const int hl   = lane & 15;
    const int node = warp * 2 + half;
    if (node >= NN) return;

    const float dinv = g_deg[node];
    const int beg = g_off[node];
    const int end = g_off[node + 1];

    float4 a = *reinterpret_cast<const float4*>(&g_h[(size_t)node * FOUT + hl * 4]);
    const float sl = dinv * dinv;
    a.x *= sl; a.y *= sl; a.z *= sl; a.w *= sl;

    int j = beg;
    for (; j + 4 <= end; j += 4) {
        int s0 = g_nbr[j];
        int s1 = g_nbr[j + 1];
        int s2 = g_nbr[j + 2];
        int s3 = g_nbr[j + 3];
        float n0 = dinv * g_deg[s0];
        float n1 = dinv * g_deg[s1];
        float n2 = dinv * g_deg[s2];
        float n3 = dinv * g_deg[s3];
        float4 v0 = *reinterpret_cast<const float4*>(&g_h[(size_t)s0 * FOUT + hl * 4]);
        float4 v1 = *reinterpret_cast<const float4*>(&g_h[(size_t)s1 * FOUT + hl * 4]);
        float4 v2 = *reinterpret_cast<const float4*>(&g_h[(size_t)s2 * FOUT + hl * 4]);
        float4 v3 = *reinterpret_cast<const float4*>(&g_h[(size_t)s3 * FOUT + hl * 4]);
        a.x = fmaf(v0.x, n0, a.x); a.y = fmaf(v0.y, n0, a.y);
        a.z = fmaf(v0.z, n0, a.z); a.w = fmaf(v0.w, n0, a.w);
        a.x = fmaf(v1.x, n1, a.x); a.y = fmaf(v1.y, n1, a.y);
        a.z = fmaf(v1.z, n1, a.z); a.w = fmaf(v1.w, n1, a.w);
        a.x = fmaf(v2.x, n2, a.x); a.y = fmaf(v2.y, n2, a.y);
        a.z = fmaf(v2.z, n2, a.z); a.w = fmaf(v2.w, n2, a.w);
        a.x = fmaf(v3.x, n3, a.x); a.y = fmaf(v3.y, n3, a.y);
        a.z = fmaf(v3.z, n3, a.z); a.w = fmaf(v3.w, n3, a.w);
    }
    for (; j < end; ++j) {
        int s0 = g_nbr[j];
        float n0 = dinv * g_deg[s0];
        float4 v0 = *reinterpret_cast<const float4*>(&g_h[(size_t)s0 * FOUT + hl * 4]);
        a.x = fmaf(v0.x, n0, a.x); a.y = fmaf(v0.y, n0, a.y);
        a.z = fmaf(v0.z, n0, a.z); a.w = fmaf(v0.w, n0, a.w);
    }

    float4 bb = *reinterpret_cast<const float4*>(bias + hl * 4);
    a.x = fmaxf(a.x + bb.x, 0.f);
    a.y = fmaxf(a.y + bb.y, 0.f);
    a.z = fmaxf(a.z + bb.z, 0.f);
    a.w = fmaxf(a.w + bb.w, 0.f);
    *reinterpret_cast<float4*>(&out[(size_t)node * FOUT + hl * 4]) = a;
}

// ---------------------------------------------------------------------------
extern "C" void kernel_launch(void* const* d_in, const int* in_sizes, int n_in,
                              void* d_out, int out_size)
{
    const float* x   = (const float*)d_in[0];   // [N, 256]
    const int*   adj = (const int*)d_in[1];     // [2, E]
    const float* W   = (const float*)d_in[2];   // [256, 64]
    const float* b   = (const float*)d_in[3];   // [64]
    float*       out = (float*)d_out;           // [N, 64]

    const int* src = adj;
    const int* dst = adj + EE;

    static bool attr_set = false;
    if (!attr_set) {
        cudaFuncSetAttribute(k_gemm_mma,
                             cudaFuncAttributeMaxDynamicSharedMemorySize, GEMM_SMEM);
        attr_set = true;
    }

    // CSR build; GEMM is independent and placed 4th so ncu profiles it.
    k_zero<<<(NN + 255) / 256, 256>>>();
    k_count<<<(EE / 4 + 255) / 256, 256>>>(dst);
    k_scan_a<<<NBLK, 1024>>>();
    k_gemm_mma<<<(NN + 127) / 128, 512, GEMM_SMEM>>>(x, W);   // 4th launch
    k_scan_c<<<NBLK, 1024>>>();
    k_fill<<<(EE / 4 + 255) / 256, 256>>>(src, dst);

    // fused gather + self loop + bias + relu
    k_gather<<<(NN / 2 + 7) / 8, 256>>>(b, out);
}

// round 11
// speedup vs baseline: 1.4345x; 1.1315x over previous
#include <cuda_runtime.h>
#include <cuda_bf16.h>
#include <cstdint>

// Problem constants (match reference_code)
#define NN 50000
#define EE 800000
#define FIN 256
#define FOUT 64

#define NBLK 49   // ceil(NN / 1024)

// Scratch (no cudaMalloc allowed) — static __device__ globals.
__device__ int   g_cnt[NN];          // in-degree (w/o self loop)
__device__ int   g_fill[NN];         // bucket fill cursor (pre-init to offsets)
__device__ int   g_off[NN + 1];      // CSR offsets
__device__ int   g_bsum[64];         // per-block sums for scan
__device__ int   g_nbr[EE];          // CSR: src node per incoming edge (4B/edge)
__device__ float g_deg[NN];          // dinv = rsqrt(deg)
__device__ float g_h[NN * FOUT];     // h = x @ W

// ---------------------------------------------------------------------------
__device__ __forceinline__ uint32_t pk2(float lo, float hi) {
    uint32_t d;
    asm("cvt.rn.bf16x2.f32 %0, %1, %2;" : "=r"(d) : "f"(hi), "f"(lo));
    return d;
}
__device__ __forceinline__ float f_lo16(uint32_t u) { return __uint_as_float(u << 16); }
__device__ __forceinline__ float f_hi16(uint32_t u) { return __uint_as_float(u & 0xffff0000u); }

__device__ __forceinline__ void mma_bf16(float* c, const uint32_t* a, uint32_t b0, uint32_t b1) {
    asm volatile(
        "mma.sync.aligned.m16n8k16.row.col.f32.bf16.bf16.f32 "
        "{%0,%1,%2,%3}, {%4,%5,%6,%7}, {%8,%9}, {%0,%1,%2,%3};"
        : "+f"(c[0]), "+f"(c[1]), "+f"(c[2]), "+f"(c[3])
        : "r"(a[0]), "r"(a[1]), "r"(a[2]), "r"(a[3]), "r"(b0), "r"(b1));
}

// ---------------------------------------------------------------------------
// K1: zero counters
__global__ void k_zero() {
    int i = blockIdx.x * blockDim.x + threadIdx.x;
    if (i < NN) g_cnt[i] = 0;
}

// K2: in-degree count over edge dst (4 edges/thread, int4 loads)
__global__ void k_count(const int* __restrict__ dst) {
    int e0 = (blockIdx.x * blockDim.x + threadIdx.x) * 4;
    if (e0 >= EE) return;
    int4 d4 = *reinterpret_cast<const int4*>(dst + e0);
    atomicAdd(&g_cnt[d4.x], 1);
    atomicAdd(&g_cnt[d4.y], 1);
    atomicAdd(&g_cnt[d4.z], 1);
    atomicAdd(&g_cnt[d4.w], 1);
}

// K3a: per-block (1024 elems) sums, coalesced
__global__ __launch_bounds__(1024) void k_scan_a() {
    __shared__ int ws[32];
    const int t = threadIdx.x;
    int idx = blockIdx.x * 1024 + t;
    int v = (idx < NN) ? g_cnt[idx] : 0;
    for (int o = 16; o > 0; o >>= 1) v += __shfl_down_sync(0xffffffffu, v, o);
    if ((t & 31) == 0) ws[t >> 5] = v;
    __syncthreads();
    if (t < 32) {
        int s = ws[t];
        for (int o = 16; o > 0; o >>= 1) s += __shfl_down_sync(0xffffffffu, s, o);
        if (t == 0) g_bsum[blockIdx.x] = s;
    }
}

// K3b: per-block exclusive scan -> g_off, g_fill (cursor), g_deg.
// Each block computes its own global prefix from g_bsum (warp 1).
__global__ __launch_bounds__(1024) void k_scan_c() {
    __shared__ int ws[32];
    __shared__ int bpre_s;
    const int t = threadIdx.x;
    const int lane = t & 31;
    const int wid = t >> 5;
    int idx = blockIdx.x * 1024 + t;
    int c = (idx < NN) ? g_cnt[idx] : 0;

    int incl = c;
    for (int o = 1; o < 32; o <<= 1) {
        int u = __shfl_up_sync(0xffffffffu, incl, o);
        if (lane >= o) incl += u;
    }
    if (lane == 31) ws[wid] = incl;

    if (wid == 1) {
        int accp = 0;
        for (int j = lane; j < blockIdx.x; j += 32) accp += g_bsum[j];
        for (int o = 16; o > 0; o >>= 1) accp += __shfl_down_sync(0xffffffffu, accp, o);
        if (lane == 0) bpre_s = accp;
    }
    __syncthreads();
    if (wid == 0) {
        int wv = ws[lane];
        for (int o = 1; o < 32; o <<= 1) {
            int u = __shfl_up_sync(0xffffffffu, wv, o);
            if (lane >= o) wv += u;
        }
        ws[lane] = wv;
    }
    __syncthreads();
    int excl = incl - c + (wid ? ws[wid - 1] : 0);

    if (idx < NN) {
        int off = bpre_s + excl;
        g_off[idx]  = off;
        g_fill[idx] = off;
        g_deg[idx]  = rsqrtf((float)(c + 1));
    }
    if (blockIdx.x == 0 && t == 0) g_off[NN] = EE;
}

// K4: bucket fill — cursor holds offsets; 4 edges/thread; 4B/edge store.
__global__ void k_fill(const int* __restrict__ src, const int* __restrict__ dst) {
    int e0 = (blockIdx.x * blockDim.x + threadIdx.x) * 4;
    if (e0 >= EE) return;
    int4 s4 = *reinterpret_cast<const int4*>(src + e0);
    int4 d4 = *reinterpret_cast<const int4*>(dst + e0);
    int p0 = atomicAdd(&g_fill[d4.x], 1);
    int p1 = atomicAdd(&g_fill[d4.y], 1);
    int p2 = atomicAdd(&g_fill[d4.z], 1);
    int p3 = atomicAdd(&g_fill[d4.w], 1);
    g_nbr[p0] = s4.x;
    g_nbr[p1] = s4.y;
    g_nbr[p2] = s4.z;
    g_nbr[p3] = s4.w;
}

// ---------------------------------------------------------------------------
// K5: mma.sync bf16 GEMM  h = x @ W  with split-bf16 — measured-best 40µs
// version: 512 thr, 16 warps = 8 m-stripes x 2 n-halves, acc[4][4],
// direct-LDG A fragments, smem bf16 hi/lo W, pk2 conversions. UNCHANGED.

#define PAD_K 264   // 256 + 8 pad: conflict-free b-frag LDS
#define B_HI_OFF 0
#define B_LO_OFF (64 * PAD_K)               // in ushort units
#define GEMM_SMEM (2 * 64 * PAD_K * 2)      // bytes = 67584

__global__ __launch_bounds__(512, 2) void k_gemm_mma(
    const float* __restrict__ x, const float* __restrict__ W)
{
    extern __shared__ __align__(16) ushort Bs[];   // [2][64][PAD_K] bf16 bits

    const int t    = threadIdx.x;
    const int wid  = t >> 5;
    const int lane = t & 31;
    const int g    = lane >> 2;
    const int tig  = lane & 3;

#pragma unroll 8
    for (int it = 0; it < 32; ++it) {
        int idx = t + it * 512;
        int k = idx >> 6;
        int n = idx & 63;
        float w = W[k * FOUT + n];
        uint32_t hp = pk2(w, 0.f);
        Bs[B_HI_OFF + n * PAD_K + k] = (ushort)(hp & 0xffffu);
        Bs[B_LO_OFF + n * PAD_K + k] =
            (ushort)(pk2(w - f_lo16(hp), 0.f) & 0xffffu);
    }
    __syncthreads();

    const int stripe = wid & 7;
    const int nhalf  = wid >> 3;
    const int row0   = blockIdx.x * 128 + stripe * 16;

    const int row1 = row0 + g;
    const int row2 = row1 + 8;
    const bool v1 = (row1 < NN);
    const bool v2 = (row2 < NN);
    const float* xr1 = x + (size_t)row1 * FIN;
    const float* xr2 = x + (size_t)row2 * FIN;

    float acc[4][4];
#pragma unroll
    for (int i = 0; i < 4; ++i)
#pragma unroll
        for (int j = 0; j < 4; ++j) acc[i][j] = 0.0f;

#pragma unroll 4
    for (int s = 0; s < 16; ++s) {
        const int kb = s * 16 + tig * 2;

        float2 p0 = v1 ? *reinterpret_cast<const float2*>(xr1 + kb)     : make_float2(0.f, 0.f);
        float2 p1 = v2 ? *reinterpret_cast<const float2*>(xr2 + kb)     : make_float2(0.f, 0.f);
        float2 p2 = v1 ? *reinterpret_cast<const float2*>(xr1 + kb + 8) : make_float2(0.f, 0.f);
        float2 p3 = v2 ? *reinterpret_cast<const float2*>(xr2 + kb + 8) : make_float2(0.f, 0.f);

        uint32_t a_hi[4], a_lo[4];
        a_hi[0] = pk2(p0.x, p0.y); a_lo[0] = pk2(p0.x - f_lo16(a_hi[0]), p0.y - f_hi16(a_hi[0]));
        a_hi[1] = pk2(p1.x, p1.y); a_lo[1] = pk2(p1.x - f_lo16(a_hi[1]), p1.y - f_hi16(a_hi[1]));
        a_hi[2] = pk2(p2.x, p2.y); a_lo[2] = pk2(p2.x - f_lo16(a_hi[2]), p2.y - f_hi16(a_hi[2]));
        a_hi[3] = pk2(p3.x, p3.y); a_lo[3] = pk2(p3.x - f_lo16(a_hi[3]), p3.y - f_hi16(a_hi[3]));

#pragma unroll
        for (int nt = 0; nt < 4; ++nt) {
            int n = nhalf * 32 + nt * 8 + g;
            const ushort* bh = &Bs[B_HI_OFF + n * PAD_K + kb];
            const ushort* bl = &Bs[B_LO_OFF + n * PAD_K + kb];
            uint32_t bh0 = *reinterpret_cast<const uint32_t*>(bh);
            uint32_t bh1 = *reinterpret_cast<const uint32_t*>(bh + 8);
            uint32_t bl0 = *reinterpret_cast<const uint32_t*>(bl);
            uint32_t bl1 = *reinterpret_cast<const uint32_t*>(bl + 8);
            mma_bf16(acc[nt], a_hi, bh0, bh1);
            mma_bf16(acc[nt], a_hi, bl0, bl1);
            mma_bf16(acc[nt], a_lo, bh0, bh1);
        }
    }

#pragma unroll
    for (int nt = 0; nt < 4; ++nt) {
        int c0 = nhalf * 32 + nt * 8 + tig * 2;
        if (v1)
            *reinterpret_cast<float2*>(&g_h[(size_t)row1 * FOUT + c0]) =
                make_float2(acc[nt][0], acc[nt][1]);
        if (v2)
            *reinterpret_cast<float2*>(&g_h[(size_t)row2 * FOUT + c0]) =
                make_float2(acc[nt][2], acc[nt][3]);
    }
}

// ---------------------------------------------------------------------------
// K6: CSR gather. 2 nodes/warp (16 lanes x float4), 4B/edge, deg loads
// in-loop (L2 broadcast), x4 unroll. UNCHANGED.
__global__ __launch_bounds__(256) void k_gather(
    const float* __restrict__ bias, float* __restrict__ out)
{
    const int warp = blockIdx.x * 8 + (threadIdx.x >> 5);
    const int lane = threadIdx.x & 31;
    const int half = lane >> 4;
    const int hl   = lane & 15;
    const int node = warp * 2 + half;
    if (node >= NN) return;

    const float dinv = g_deg[node];
    const int beg = g_off[node];
    const int end = g_off[node + 1];

    float4 a = *reinterpret_cast<const float4*>(&g_h[(size_t)node * FOUT + hl * 4]);
    const float sl = dinv * dinv;
    a.x *= sl; a.y *= sl; a.z *= sl; a.w *= sl;

    int j = beg;
    for (; j + 4 <= end; j += 4) {
        int s0 = g_nbr[j];
        int s1 = g_nbr[j + 1];
        int s2 = g_nbr[j + 2];
        int s3 = g_nbr[j + 3];
        float n0 = dinv * g_deg[s0];
        float n1 = dinv * g_deg[s1];
        float n2 = dinv * g_deg[s2];
        float n3 = dinv * g_deg[s3];
        float4 v0 = *reinterpret_cast<const float4*>(&g_h[(size_t)s0 * FOUT + hl * 4]);
        float4 v1 = *reinterpret_cast<const float4*>(&g_h[(size_t)s1 * FOUT + hl * 4]);
        float4 v2 = *reinterpret_cast<const float4*>(&g_h[(size_t)s2 * FOUT + hl * 4]);
        float4 v3 = *reinterpret_cast<const float4*>(&g_h[(size_t)s3 * FOUT + hl * 4]);
        a.x = fmaf(v0.x, n0, a.x); a.y = fmaf(v0.y, n0, a.y);
        a.z = fmaf(v0.z, n0, a.z); a.w = fmaf(v0.w, n0, a.w);
        a.x = fmaf(v1.x, n1, a.x); a.y = fmaf(v1.y, n1, a.y);
        a.z = fmaf(v1.z, n1, a.z); a.w = fmaf(v1.w, n1, a.w);
        a.x = fmaf(v2.x, n2, a.x); a.y = fmaf(v2.y, n2, a.y);
        a.z = fmaf(v2.z, n2, a.z); a.w = fmaf(v2.w, n2, a.w);
        a.x = fmaf(v3.x, n3, a.x); a.y = fmaf(v3.y, n3, a.y);
        a.z = fmaf(v3.z, n3, a.z); a.w = fmaf(v3.w, n3, a.w);
    }
    for (; j < end; ++j) {
        int s0 = g_nbr[j];
        float n0 = dinv * g_deg[s0];
        float4 v0 = *reinterpret_cast<const float4*>(&g_h[(size_t)s0 * FOUT + hl * 4]);
        a.x = fmaf(v0.x, n0, a.x); a.y = fmaf(v0.y, n0, a.y);
        a.z = fmaf(v0.z, n0, a.z); a.w = fmaf(v0.w, n0, a.w);
    }

    float4 bb = *reinterpret_cast<const float4*>(bias + hl * 4);
    a.x = fmaxf(a.x + bb.x, 0.f);
    a.y = fmaxf(a.y + bb.y, 0.f);
    a.z = fmaxf(a.z + bb.z, 0.f);
    a.w = fmaxf(a.w + bb.w, 0.f);
    *reinterpret_cast<float4*>(&out[(size_t)node * FOUT + hl * 4]) = a;
}

// ---------------------------------------------------------------------------
// Launch topology: fork a second (non-blocking) stream for the CSR build so
// it runs CONCURRENTLY with the independent GEMM; join before the gather.
// Event-linked fork/join is graph-capture legal and becomes parallel graph
// branches. Streams/events are created once (host-side resources only).
extern "C" void kernel_launch(void* const* d_in, const int* in_sizes, int n_in,
                              void* d_out, int out_size)
{
    const float* x   = (const float*)d_in[0];   // [N, 256]
    const int*   adj = (const int*)d_in[1];     // [2, E]
    const float* W   = (const float*)d_in[2];   // [256, 64]
    const float* b   = (const float*)d_in[3];   // [64]
    float*       out = (float*)d_out;           // [N, 64]

    const int* src = adj;
    const int* dst = adj + EE;

    static cudaStream_t s2 = nullptr;
    static cudaEvent_t evF = nullptr, evJ = nullptr;
    if (!s2) {
        cudaStreamCreateWithFlags(&s2, cudaStreamNonBlocking);
        cudaEventCreateWithFlags(&evF, cudaEventDisableTiming);
        cudaEventCreateWithFlags(&evJ, cudaEventDisableTiming);
        cudaFuncSetAttribute(k_gemm_mma,
                             cudaFuncAttributeMaxDynamicSharedMemorySize, GEMM_SMEM);
    }

    // fork: s2 branch starts after the capture-stream front
    cudaEventRecord(evF, 0);
    cudaStreamWaitEvent(s2, evF, 0);

    // branch B (s2): CSR build chain
    k_zero<<<(NN + 255) / 256, 256, 0, s2>>>();
    k_count<<<(EE / 4 + 255) / 256, 256, 0, s2>>>(dst);
    k_scan_a<<<NBLK, 1024, 0, s2>>>();
    k_scan_c<<<NBLK, 1024, 0, s2>>>();
    k_fill<<<(EE / 4 + 255) / 256, 256, 0, s2>>>(src, dst);
    cudaEventRecord(evJ, s2);

    // branch A (main stream): GEMM, independent of CSR build
    k_gemm_mma<<<(NN + 127) / 128, 512, GEMM_SMEM>>>(x, W);

    // join: gather needs both branches
    cudaStreamWaitEvent(0, evJ, 0);
    k_gather<<<(NN / 2 + 7) / 8, 256>>>(b, out);
}

// round 12
// speedup vs baseline: 1.4724x; 1.0265x over previous
#include <cuda_runtime.h>
#include <cuda_bf16.h>
#include <cuda_fp16.h>
#include <cstdint>

// Problem constants (match reference_code)
#define NN 50000
#define EE 800000
#define FIN 256
#define FOUT 64

#define NBLK 49   // ceil(NN / 1024)

// Scratch (no cudaMalloc allowed) — static __device__ globals.
__device__ int    g_cnt[NN];          // in-degree (w/o self loop)
__device__ int    g_fill[NN];         // bucket fill cursor (pre-init to offsets)
__device__ int    g_off[NN + 1];      // CSR offsets
__device__ int    g_bsum[64];         // per-block sums for scan
__device__ int    g_nbr[EE];          // CSR: src node per incoming edge (4B/edge)
__device__ float  g_deg[NN];          // dinv = rsqrt(deg)
__device__ __half g_h16[NN * FOUT];   // h = x @ W, fp16 (128B per row)

// ---------------------------------------------------------------------------
__device__ __forceinline__ uint32_t pk2(float lo, float hi) {
    uint32_t d;
    asm("cvt.rn.bf16x2.f32 %0, %1, %2;" : "=r"(d) : "f"(hi), "f"(lo));
    return d;
}
__device__ __forceinline__ float f_lo16(uint32_t u) { return __uint_as_float(u << 16); }
__device__ __forceinline__ float f_hi16(uint32_t u) { return __uint_as_float(u & 0xffff0000u); }

__device__ __forceinline__ void mma_bf16(float* c, const uint32_t* a, uint32_t b0, uint32_t b1) {
    asm volatile(
        "mma.sync.aligned.m16n8k16.row.col.f32.bf16.bf16.f32 "
        "{%0,%1,%2,%3}, {%4,%5,%6,%7}, {%8,%9}, {%0,%1,%2,%3};"
        : "+f"(c[0]), "+f"(c[1]), "+f"(c[2]), "+f"(c[3])
        : "r"(a[0]), "r"(a[1]), "r"(a[2]), "r"(a[3]), "r"(b0), "r"(b1));
}

// ---------------------------------------------------------------------------
// K1: zero counters
__global__ void k_zero() {
    int i = blockIdx.x * blockDim.x + threadIdx.x;
    if (i < NN) g_cnt[i] = 0;
}

// K2: in-degree count over edge dst (4 edges/thread, int4 loads)
__global__ void k_count(const int* __restrict__ dst) {
    int e0 = (blockIdx.x * blockDim.x + threadIdx.x) * 4;
    if (e0 >= EE) return;
    int4 d4 = *reinterpret_cast<const int4*>(dst + e0);
    atomicAdd(&g_cnt[d4.x], 1);
    atomicAdd(&g_cnt[d4.y], 1);
    atomicAdd(&g_cnt[d4.z], 1);
    atomicAdd(&g_cnt[d4.w], 1);
}

// K3a: per-block (1024 elems) sums, coalesced
__global__ __launch_bounds__(1024) void k_scan_a() {
    __shared__ int ws[32];
    const int t = threadIdx.x;
    int idx = blockIdx.x * 1024 + t;
    int v = (idx < NN) ? g_cnt[idx] : 0;
    for (int o = 16; o > 0; o >>= 1) v += __shfl_down_sync(0xffffffffu, v, o);
    if ((t & 31) == 0) ws[t >> 5] = v;
    __syncthreads();
    if (t < 32) {
        int s = ws[t];
        for (int o = 16; o > 0; o >>= 1) s += __shfl_down_sync(0xffffffffu, s, o);
        if (t == 0) g_bsum[blockIdx.x] = s;
    }
}

// K3b: per-block exclusive scan -> g_off, g_fill (cursor), g_deg.
__global__ __launch_bounds__(1024) void k_scan_c() {
    __shared__ int ws[32];
    __shared__ int bpre_s;
    const int t = threadIdx.x;
    const int lane = t & 31;
    const int wid = t >> 5;
    int idx = blockIdx.x * 1024 + t;
    int c = (idx < NN) ? g_cnt[idx] : 0;

    int incl = c;
    for (int o = 1; o < 32; o <<= 1) {
        int u = __shfl_up_sync(0xffffffffu, incl, o);
        if (lane >= o) incl += u;
    }
    if (lane == 31) ws[wid] = incl;

    if (wid == 1) {
        int accp = 0;
        for (int j = lane; j < blockIdx.x; j += 32) accp += g_bsum[j];
        for (int o = 16; o > 0; o >>= 1) accp += __shfl_down_sync(0xffffffffu, accp, o);
        if (lane == 0) bpre_s = accp;
    }
    __syncthreads();
    if (wid == 0) {
        int wv = ws[lane];
        for (int o = 1; o < 32; o <<= 1) {
            int u = __shfl_up_sync(0xffffffffu, wv, o);
            if (lane >= o) wv += u;
        }
        ws[lane] = wv;
    }
    __syncthreads();
    int excl = incl - c + (wid ? ws[wid - 1] : 0);

    if (idx < NN) {
        int off = bpre_s + excl;
        g_off[idx]  = off;
        g_fill[idx] = off;
        g_deg[idx]  = rsqrtf((float)(c + 1));
    }
    if (blockIdx.x == 0 && t == 0) g_off[NN] = EE;
}

// K4: bucket fill — cursor holds offsets; 4 edges/thread; 4B/edge store.
__global__ void k_fill(const int* __restrict__ src, const int* __restrict__ dst) {
    int e0 = (blockIdx.x * blockDim.x + threadIdx.x) * 4;
    if (e0 >= EE) return;
    int4 s4 = *reinterpret_cast<const int4*>(src + e0);
    int4 d4 = *reinterpret_cast<const int4*>(dst + e0);
    int p0 = atomicAdd(&g_fill[d4.x], 1);
    int p1 = atomicAdd(&g_fill[d4.y], 1);
    int p2 = atomicAdd(&g_fill[d4.z], 1);
    int p3 = atomicAdd(&g_fill[d4.w], 1);
    g_nbr[p0] = s4.x;
    g_nbr[p1] = s4.y;
    g_nbr[p2] = s4.z;
    g_nbr[p3] = s4.w;
}

// ---------------------------------------------------------------------------
// K5: mma.sync bf16 GEMM  h = x @ W  with split-bf16 — measured-best 40µs
// structure. ONLY change: epilogue stores h as fp16 (halves h traffic for
// the gather and halves the epilogue store).

#define PAD_K 264   // 256 + 8 pad: conflict-free b-frag LDS
#define B_HI_OFF 0
#define B_LO_OFF (64 * PAD_K)               // in ushort units
#define GEMM_SMEM (2 * 64 * PAD_K * 2)      // bytes = 67584

__global__ __launch_bounds__(512, 2) void k_gemm_mma(
    const float* __restrict__ x, const float* __restrict__ W)
{
    extern __shared__ __align__(16) ushort Bs[];   // [2][64][PAD_K] bf16 bits

    const int t    = threadIdx.x;
    const int wid  = t >> 5;
    const int lane = t & 31;
    const int g    = lane >> 2;
    const int tig  = lane & 3;

#pragma unroll 8
    for (int it = 0; it < 32; ++it) {
        int idx = t + it * 512;
        int k = idx >> 6;
        int n = idx & 63;
        float w = W[k * FOUT + n];
        uint32_t hp = pk2(w, 0.f);
        Bs[B_HI_OFF + n * PAD_K + k] = (ushort)(hp & 0xffffu);
        Bs[B_LO_OFF + n * PAD_K + k] =
            (ushort)(pk2(w - f_lo16(hp), 0.f) & 0xffffu);
    }
    __syncthreads();

    const int stripe = wid & 7;
    const int nhalf  = wid >> 3;
    const int row0   = blockIdx.x * 128 + stripe * 16;

    const int row1 = row0 + g;
    const int row2 = row1 + 8;
    const bool v1 = (row1 < NN);
    const bool v2 = (row2 < NN);
    const float* xr1 = x + (size_t)row1 * FIN;
    const float* xr2 = x + (size_t)row2 * FIN;

    float acc[4][4];
#pragma unroll
    for (int i = 0; i < 4; ++i)
#pragma unroll
        for (int j = 0; j < 4; ++j) acc[i][j] = 0.0f;

#pragma unroll 4
    for (int s = 0; s < 16; ++s) {
        const int kb = s * 16 + tig * 2;

        float2 p0 = v1 ? *reinterpret_cast<const float2*>(xr1 + kb)     : make_float2(0.f, 0.f);
        float2 p1 = v2 ? *reinterpret_cast<const float2*>(xr2 + kb)     : make_float2(0.f, 0.f);
        float2 p2 = v1 ? *reinterpret_cast<const float2*>(xr1 + kb + 8) : make_float2(0.f, 0.f);
        float2 p3 = v2 ? *reinterpret_cast<const float2*>(xr2 + kb + 8) : make_float2(0.f, 0.f);

        uint32_t a_hi[4], a_lo[4];
        a_hi[0] = pk2(p0.x, p0.y); a_lo[0] = pk2(p0.x - f_lo16(a_hi[0]), p0.y - f_hi16(a_hi[0]));
        a_hi[1] = pk2(p1.x, p1.y); a_lo[1] = pk2(p1.x - f_lo16(a_hi[1]), p1.y - f_hi16(a_hi[1]));
        a_hi[2] = pk2(p2.x, p2.y); a_lo[2] = pk2(p2.x - f_lo16(a_hi[2]), p2.y - f_hi16(a_hi[2]));
        a_hi[3] = pk2(p3.x, p3.y); a_lo[3] = pk2(p3.x - f_lo16(a_hi[3]), p3.y - f_hi16(a_hi[3]));

#pragma unroll
        for (int nt = 0; nt < 4; ++nt) {
            int n = nhalf * 32 + nt * 8 + g;
            const ushort* bh = &Bs[B_HI_OFF + n * PAD_K + kb];
            const ushort* bl = &Bs[B_LO_OFF + n * PAD_K + kb];
            uint32_t bh0 = *reinterpret_cast<const uint32_t*>(bh);
            uint32_t bh1 = *reinterpret_cast<const uint32_t*>(bh + 8);
            uint32_t bl0 = *reinterpret_cast<const uint32_t*>(bl);
            uint32_t bl1 = *reinterpret_cast<const uint32_t*>(bl + 8);
            mma_bf16(acc[nt], a_hi, bh0, bh1);
            mma_bf16(acc[nt], a_hi, bl0, bl1);
            mma_bf16(acc[nt], a_lo, bh0, bh1);
        }
    }

    // ---- epilogue: write h as fp16 (half2 per (nt, row)) ----
#pragma unroll
    for (int nt = 0; nt < 4; ++nt) {
        int c0 = nhalf * 32 + nt * 8 + tig * 2;   // even
        if (v1) {
            __half2 hv = __floats2half2_rn(acc[nt][0], acc[nt][1]);
            *reinterpret_cast<__half2*>(&g_h16[(size_t)row1 * FOUT + c0]) = hv;
        }
        if (v2) {
            __half2 hv = __floats2half2_rn(acc[nt][2], acc[nt][3]);
            *reinterpret_cast<__half2*>(&g_h16[(size_t)row2 * FOUT + c0]) = hv;
        }
    }
}

// ---------------------------------------------------------------------------
// K6: CSR gather on fp16 h (128B rows). 2 nodes/warp: 16 lanes x 4 halfs
// (uint2) each. fp32 accumulation. deg in-loop, x4 unroll.
__global__ __launch_bounds__(256) void k_gather(
    const float* __restrict__ bias, float* __restrict__ out)
{
    const int warp = blockIdx.x * 8 + (threadIdx.x >> 5);
    const int lane = threadIdx.x & 31;
    const int half = lane >> 4;
    const int hl   = lane & 15;
    const int node = warp * 2 + half;
    if (node >= NN) return;

    const float dinv = g_deg[node];
    const int beg = g_off[node];
    const int end = g_off[node + 1];

    // self-loop term (fp16 h, fp32 accumulate)
    uint2 su = *reinterpret_cast<const uint2*>(&g_h16[(size_t)node * FOUT + hl * 4]);
    float2 s01 = __half22float2(*reinterpret_cast<__half2*>(&su.x));
    float2 s23 = __half22float2(*reinterpret_cast<__half2*>(&su.y));
    const float sl = dinv * dinv;
    float4 a = make_float4(s01.x * sl, s01.y * sl, s23.x * sl, s23.y * sl);

    int j = beg;
    for (; j + 4 <= end; j += 4) {
        int s0 = g_nbr[j];
        int s1 = g_nbr[j + 1];
        int s2 = g_nbr[j + 2];
        int s3 = g_nbr[j + 3];
        float n0 = dinv * g_deg[s0];
        float n1 = dinv * g_deg[s1];
        float n2 = dinv * g_deg[s2];
        float n3 = dinv * g_deg[s3];
        uint2 u0 = *reinterpret_cast<const uint2*>(&g_h16[(size_t)s0 * FOUT + hl * 4]);
        uint2 u1 = *reinterpret_cast<const uint2*>(&g_h16[(size_t)s1 * FOUT + hl * 4]);
        uint2 u2 = *reinterpret_cast<const uint2*>(&g_h16[(size_t)s2 * FOUT + hl * 4]);
        uint2 u3 = *reinterpret_cast<const uint2*>(&g_h16[(size_t)s3 * FOUT + hl * 4]);

        float2 f0a = __half22float2(*reinterpret_cast<__half2*>(&u0.x));
        float2 f0b = __half22float2(*reinterpret_cast<__half2*>(&u0.y));
        a.x = fmaf(f0a.x, n0, a.x); a.y = fmaf(f0a.y, n0, a.y);
        a.z = fmaf(f0b.x, n0, a.z); a.w = fmaf(f0b.y, n0, a.w);

        float2 f1a = __half22float2(*reinterpret_cast<__half2*>(&u1.x));
        float2 f1b = __half22float2(*reinterpret_cast<__half2*>(&u1.y));
        a.x = fmaf(f1a.x, n1, a.x); a.y = fmaf(f1a.y, n1, a.y);
        a.z = fmaf(f1b.x, n1, a.z); a.w = fmaf(f1b.y, n1, a.w);

        float2 f2a = __half22float2(*reinterpret_cast<__half2*>(&u2.x));
        float2 f2b = __half22float2(*reinterpret_cast<__half2*>(&u2.y));
        a.x = fmaf(f2a.x, n2, a.x); a.y = fmaf(f2a.y, n2, a.y);
        a.z = fmaf(f2b.x, n2, a.z); a.w = fmaf(f2b.y, n2, a.w);

        float2 f3a = __half22float2(*reinterpret_cast<__half2*>(&u3.x));
        float2 f3b = __half22float2(*reinterpret_cast<__half2*>(&u3.y));
        a.x = fmaf(f3a.x, n3, a.x); a.y = fmaf(f3a.y, n3, a.y);
        a.z = fmaf(f3b.x, n3, a.z); a.w = fmaf(f3b.y, n3, a.w);
    }
    for (; j < end; ++j) {
        int s0 = g_nbr[j];
        float n0 = dinv * g_deg[s0];
        uint2 u0 = *reinterpret_cast<const uint2*>(&g_h16[(size_t)s0 * FOUT + hl * 4]);
        float2 f0a = __half22float2(*reinterpret_cast<__half2*>(&u0.x));
        float2 f0b = __half22float2(*reinterpret_cast<__half2*>(&u0.y));
        a.x = fmaf(f0a.x, n0, a.x); a.y = fmaf(f0a.y, n0, a.y);
        a.z = fmaf(f0b.x, n0, a.z); a.w = fmaf(f0b.y, n0, a.w);
    }

    float4 bb = *reinterpret_cast<const float4*>(bias + hl * 4);
    a.x = fmaxf(a.x + bb.x, 0.f);
    a.y = fmaxf(a.y + bb.y, 0.f);
    a.z = fmaxf(a.z + bb.z, 0.f);
    a.w = fmaxf(a.w + bb.w, 0.f);
    *reinterpret_cast<float4*>(&out[(size_t)node * FOUT + hl * 4]) = a;
}

// ---------------------------------------------------------------------------
// Launch topology: unchanged fork/join (CSR build concurrent with GEMM).
extern "C" void kernel_launch(void* const* d_in, const int* in_sizes, int n_in,
                              void* d_out, int out_size)
{
    const float* x   = (const float*)d_in[0];   // [N, 256]
    const int*   adj = (const int*)d_in[1];     // [2, E]
    const float* W   = (const float*)d_in[2];   // [256, 64]
    const float* b   = (const float*)d_in[3];   // [64]
    float*       out = (float*)d_out;           // [N, 64]

    const int* src = adj;
    const int* dst = adj + EE;

    static cudaStream_t s2 = nullptr;
    static cudaEvent_t evF = nullptr, evJ = nullptr;
    if (!s2) {
        cudaStreamCreateWithFlags(&s2, cudaStreamNonBlocking);
        cudaEventCreateWithFlags(&evF, cudaEventDisableTiming);
        cudaEventCreateWithFlags(&evJ, cudaEventDisableTiming);
        cudaFuncSetAttribute(k_gemm_mma,
                             cudaFuncAttributeMaxDynamicSharedMemorySize, GEMM_SMEM);
    }

    // fork: s2 branch starts after the capture-stream front
    cudaEventRecord(evF, 0);
    cudaStreamWaitEvent(s2, evF, 0);

    // branch B (s2): CSR build chain
    k_zero<<<(NN + 255) / 256, 256, 0, s2>>>();
    k_count<<<(EE / 4 + 255) / 256, 256, 0, s2>>>(dst);
    k_scan_a<<<NBLK, 1024, 0, s2>>>();
    k_scan_c<<<NBLK, 1024, 0, s2>>>();
    k_fill<<<(EE / 4 + 255) / 256, 256, 0, s2>>>(src, dst);
    cudaEventRecord(evJ, s2);

    // branch A (main stream): GEMM, independent of CSR build
    k_gemm_mma<<<(NN + 127) / 128, 512, GEMM_SMEM>>>(x, W);

    // join: gather needs both branches
    cudaStreamWaitEvent(0, evJ, 0);
    k_gather<<<(NN / 2 + 7) / 8, 256>>>(b, out);
}

// round 13
// speedup vs baseline: 1.4895x; 1.0116x over previous
#include <cuda_runtime.h>
#include <cuda_bf16.h>
#include <cuda_fp16.h>
#include <cstdint>

// Problem constants (match reference_code)
#define NN 50000
#define EE 800000
#define FIN 256
#define FOUT 64

#define NBLK 49   // ceil(NN / 1024)

// Scratch (no cudaMalloc allowed) — static __device__ globals.
__device__ int    g_cnt[NN];          // in-degree (w/o self loop)
__device__ int    g_fill[NN];         // bucket fill cursor (pre-init to offsets)
__device__ int    g_off[NN + 1];      // CSR offsets
__device__ int    g_bsum[64];         // per-block sums for scan
__device__ int    g_nbr[EE];          // CSR: src node per incoming edge (4B/edge)
__device__ float  g_deg[NN];          // dinv = rsqrt(deg)
__device__ __half g_h16[NN * FOUT];   // h = x @ W, fp16 (128B per row)

// ---------------------------------------------------------------------------
__device__ __forceinline__ uint32_t pk2(float lo, float hi) {
    uint32_t d;
    asm("cvt.rn.bf16x2.f32 %0, %1, %2;" : "=r"(d) : "f"(hi), "f"(lo));
    return d;
}
__device__ __forceinline__ float f_lo16(uint32_t u) { return __uint_as_float(u << 16); }
__device__ __forceinline__ float f_hi16(uint32_t u) { return __uint_as_float(u & 0xffff0000u); }

__device__ __forceinline__ void mma_bf16(float* c, const uint32_t* a, uint32_t b0, uint32_t b1) {
    asm volatile(
        "mma.sync.aligned.m16n8k16.row.col.f32.bf16.bf16.f32 "
        "{%0,%1,%2,%3}, {%4,%5,%6,%7}, {%8,%9}, {%0,%1,%2,%3};"
        : "+f"(c[0]), "+f"(c[1]), "+f"(c[2]), "+f"(c[3])
        : "r"(a[0]), "r"(a[1]), "r"(a[2]), "r"(a[3]), "r"(b0), "r"(b1));
}

// ---------------------------------------------------------------------------
// K1: zero counters
__global__ void k_zero() {
    int i = blockIdx.x * blockDim.x + threadIdx.x;
    if (i < NN) g_cnt[i] = 0;
}

// K2: in-degree count over edge dst (4 edges/thread, int4 loads)
__global__ void k_count(const int* __restrict__ dst) {
    int e0 = (blockIdx.x * blockDim.x + threadIdx.x) * 4;
    if (e0 >= EE) return;
    int4 d4 = *reinterpret_cast<const int4*>(dst + e0);
    atomicAdd(&g_cnt[d4.x], 1);
    atomicAdd(&g_cnt[d4.y], 1);
    atomicAdd(&g_cnt[d4.z], 1);
    atomicAdd(&g_cnt[d4.w], 1);
}

// K3a: per-block (1024 elems) sums, coalesced
__global__ __launch_bounds__(1024) void k_scan_a() {
    __shared__ int ws[32];
    const int t = threadIdx.x;
    int idx = blockIdx.x * 1024 + t;
    int v = (idx < NN) ? g_cnt[idx] : 0;
    for (int o = 16; o > 0; o >>= 1) v += __shfl_down_sync(0xffffffffu, v, o);
    if ((t & 31) == 0) ws[t >> 5] = v;
    __syncthreads();
    if (t < 32) {
        int s = ws[t];
        for (int o = 16; o > 0; o >>= 1) s += __shfl_down_sync(0xffffffffu, s, o);
        if (t == 0) g_bsum[blockIdx.x] = s;
    }
}

// K3b: per-block exclusive scan -> g_off, g_fill (cursor), g_deg.
__global__ __launch_bounds__(1024) void k_scan_c() {
    __shared__ int ws[32];
    __shared__ int bpre_s;
    const int t = threadIdx.x;
    const int lane = t & 31;
    const int wid = t >> 5;
    int idx = blockIdx.x * 1024 + t;
    int c = (idx < NN) ? g_cnt[idx] : 0;

    int incl = c;
    for (int o = 1; o < 32; o <<= 1) {
        int u = __shfl_up_sync(0xffffffffu, incl, o);
        if (lane >= o) incl += u;
    }
    if (lane == 31) ws[wid] = incl;

    if (wid == 1) {
        int accp = 0;
        for (int j = lane; j < blockIdx.x; j += 32) accp += g_bsum[j];
        for (int o = 16; o > 0; o >>= 1) accp += __shfl_down_sync(0xffffffffu, accp, o);
        if (lane == 0) bpre_s = accp;
    }
    __syncthreads();
    if (wid == 0) {
        int wv = ws[lane];
        for (int o = 1; o < 32; o <<= 1) {
            int u = __shfl_up_sync(0xffffffffu, wv, o);
            if (lane >= o) wv += u;
        }
        ws[lane] = wv;
    }
    __syncthreads();
    int excl = incl - c + (wid ? ws[wid - 1] : 0);

    if (idx < NN) {
        int off = bpre_s + excl;
        g_off[idx]  = off;
        g_fill[idx] = off;
        g_deg[idx]  = rsqrtf((float)(c + 1));
    }
    if (blockIdx.x == 0 && t == 0) g_off[NN] = EE;
}

// K4: bucket fill — cursor holds offsets; 4 edges/thread; 4B/edge store.
__global__ void k_fill(const int* __restrict__ src, const int* __restrict__ dst) {
    int e0 = (blockIdx.x * blockDim.x + threadIdx.x) * 4;
    if (e0 >= EE) return;
    int4 s4 = *reinterpret_cast<const int4*>(src + e0);
    int4 d4 = *reinterpret_cast<const int4*>(dst + e0);
    int p0 = atomicAdd(&g_fill[d4.x], 1);
    int p1 = atomicAdd(&g_fill[d4.y], 1);
    int p2 = atomicAdd(&g_fill[d4.z], 1);
    int p3 = atomicAdd(&g_fill[d4.w], 1);
    g_nbr[p0] = s4.x;
    g_nbr[p1] = s4.y;
    g_nbr[p2] = s4.z;
    g_nbr[p3] = s4.w;
}

// ---------------------------------------------------------------------------
// K5: mma.sync bf16 GEMM with split-bf16 and PERMUTED-K fragments:
// logical mma k-lane (tig*2+j / tig*2+8+j) maps to actual k = s*16+tig*4+{j, 2+j}.
// A: one float4 per row per k-step (quad = 64B contiguous) -> 2 LDG.128/step.
// B: fragment = 4 contiguous ushorts -> 1 LDS.64 (hi) + 1 LDS.64 (lo) per nt.
// PAD_K=272: n-stride 136 words ≡ 8 mod 32 -> conflict-free LDS.64 phases.

#define PAD_K 272
#define B_HI_OFF 0
#define B_LO_OFF (64 * PAD_K)               // in ushort units
#define GEMM_SMEM (2 * 64 * PAD_K * 2)      // bytes = 69632

__global__ __launch_bounds__(512, 2) void k_gemm_mma(
    const float* __restrict__ x, const float* __restrict__ W)
{
    extern __shared__ __align__(16) ushort Bs[];   // [2][64][PAD_K] bf16 bits

    const int t    = threadIdx.x;
    const int wid  = t >> 5;
    const int lane = t & 31;
    const int g    = lane >> 2;
    const int tig  = lane & 3;

    // ---- stage W -> smem bf16 hi/lo, [n][k] layout (plain k order) ----
#pragma unroll 8
    for (int it = 0; it < 32; ++it) {
        int idx = t + it * 512;
        int k = idx >> 6;
        int n = idx & 63;
        float w = W[k * FOUT + n];
        uint32_t hp = pk2(w, 0.f);
        Bs[B_HI_OFF + n * PAD_K + k] = (ushort)(hp & 0xffffu);
        Bs[B_LO_OFF + n * PAD_K + k] =
            (ushort)(pk2(w - f_lo16(hp), 0.f) & 0xffffu);
    }
    __syncthreads();

    const int stripe = wid & 7;
    const int nhalf  = wid >> 3;
    const int row0   = blockIdx.x * 128 + stripe * 16;

    const int row1 = row0 + g;
    const int row2 = row1 + 8;
    const bool v1 = (row1 < NN);
    const bool v2 = (row2 < NN);
    const float* xr1 = x + (size_t)row1 * FIN;
    const float* xr2 = x + (size_t)row2 * FIN;

    float acc[4][4];
#pragma unroll
    for (int i = 0; i < 4; ++i)
#pragma unroll
        for (int j = 0; j < 4; ++j) acc[i][j] = 0.0f;

#pragma unroll 4
    for (int s = 0; s < 16; ++s) {
        const int kb4 = s * 16 + tig * 4;    // permuted-k fragment base

        float4 q1 = v1 ? *reinterpret_cast<const float4*>(xr1 + kb4)
                       : make_float4(0.f, 0.f, 0.f, 0.f);
        float4 q2 = v2 ? *reinterpret_cast<const float4*>(xr2 + kb4)
                       : make_float4(0.f, 0.f, 0.f, 0.f);

        uint32_t a_hi[4], a_lo[4];
        a_hi[0] = pk2(q1.x, q1.y); a_lo[0] = pk2(q1.x - f_lo16(a_hi[0]), q1.y - f_hi16(a_hi[0]));
        a_hi[1] = pk2(q2.x, q2.y); a_lo[1] = pk2(q2.x - f_lo16(a_hi[1]), q2.y - f_hi16(a_hi[1]));
        a_hi[2] = pk2(q1.z, q1.w); a_lo[2] = pk2(q1.z - f_lo16(a_hi[2]), q1.w - f_hi16(a_hi[2]));
        a_hi[3] = pk2(q2.z, q2.w); a_lo[3] = pk2(q2.z - f_lo16(a_hi[3]), q2.w - f_hi16(a_hi[3]));

#pragma unroll
        for (int nt = 0; nt < 4; ++nt) {
            int n = nhalf * 32 + nt * 8 + g;
            uint2 bh = *reinterpret_cast<const uint2*>(&Bs[B_HI_OFF + n * PAD_K + kb4]);
            uint2 bl = *reinterpret_cast<const uint2*>(&Bs[B_LO_OFF + n * PAD_K + kb4]);
            mma_bf16(acc[nt], a_hi, bh.x, bh.y);
            mma_bf16(acc[nt], a_hi, bl.x, bl.y);
            mma_bf16(acc[nt], a_lo, bh.x, bh.y);
        }
    }

    // ---- epilogue: write h as fp16 ----
#pragma unroll
    for (int nt = 0; nt < 4; ++nt) {
        int c0 = nhalf * 32 + nt * 8 + tig * 2;
        if (v1) {
            __half2 hv = __floats2half2_rn(acc[nt][0], acc[nt][1]);
            *reinterpret_cast<__half2*>(&g_h16[(size_t)row1 * FOUT + c0]) = hv;
        }
        if (v2) {
            __half2 hv = __floats2half2_rn(acc[nt][2], acc[nt][3]);
            *reinterpret_cast<__half2*>(&g_h16[(size_t)row2 * FOUT + c0]) = hv;
        }
    }
}

// ---------------------------------------------------------------------------
// K6: CSR gather on fp16 h (128B rows). 2 nodes/warp, fp32 accumulation,
// deg in-loop, x4 unroll. UNCHANGED.
__global__ __launch_bounds__(256) void k_gather(
    const float* __restrict__ bias, float* __restrict__ out)
{
    const int warp = blockIdx.x * 8 + (threadIdx.x >> 5);
    const int lane = threadIdx.x & 31;
    const int half = lane >> 4;
    const int hl   = lane & 15;
    const int node = warp * 2 + half;
    if (node >= NN) return;

    const float dinv = g_deg[node];
    const int beg = g_off[node];
    const int end = g_off[node + 1];

    uint2 su = *reinterpret_cast<const uint2*>(&g_h16[(size_t)node * FOUT + hl * 4]);
    float2 s01 = __half22float2(*reinterpret_cast<__half2*>(&su.x));
    float2 s23 = __half22float2(*reinterpret_cast<__half2*>(&su.y));
    const float sl = dinv * dinv;
    float4 a = make_float4(s01.x * sl, s01.y * sl, s23.x * sl, s23.y * sl);

    int j = beg;
    for (; j + 4 <= end; j += 4) {
        int s0 = g_nbr[j];
        int s1 = g_nbr[j + 1];
        int s2 = g_nbr[j + 2];
        int s3 = g_nbr[j + 3];
        float n0 = dinv * g_deg[s0];
        float n1 = dinv * g_deg[s1];
        float n2 = dinv * g_deg[s2];
        float n3 = dinv * g_deg[s3];
        uint2 u0 = *reinterpret_cast<const uint2*>(&g_h16[(size_t)s0 * FOUT + hl * 4]);
        uint2 u1 = *reinterpret_cast<const uint2*>(&g_h16[(size_t)s1 * FOUT + hl * 4]);
        uint2 u2 = *reinterpret_cast<const uint2*>(&g_h16[(size_t)s2 * FOUT + hl * 4]);
        uint2 u3 = *reinterpret_cast<const uint2*>(&g_h16[(size_t)s3 * FOUT + hl * 4]);

        float2 f0a = __half22float2(*reinterpret_cast<__half2*>(&u0.x));
        float2 f0b = __half22float2(*reinterpret_cast<__half2*>(&u0.y));
        a.x = fmaf(f0a.x, n0, a.x); a.y = fmaf(f0a.y, n0, a.y);
        a.z = fmaf(f0b.x, n0, a.z); a.w = fmaf(f0b.y, n0, a.w);

        float2 f1a = __half22float2(*reinterpret_cast<__half2*>(&u1.x));
        float2 f1b = __half22float2(*reinterpret_cast<__half2*>(&u1.y));
        a.x = fmaf(f1a.x, n1, a.x); a.y = fmaf(f1a.y, n1, a.y);
        a.z = fmaf(f1b.x, n1, a.z); a.w = fmaf(f1b.y, n1, a.w);

        float2 f2a = __half22float2(*reinterpret_cast<__half2*>(&u2.x));
        float2 f2b = __half22float2(*reinterpret_cast<__half2*>(&u2.y));
        a.x = fmaf(f2a.x, n2, a.x); a.y = fmaf(f2a.y, n2, a.y);
        a.z = fmaf(f2b.x, n2, a.z); a.w = fmaf(f2b.y, n2, a.w);

        float2 f3a = __half22float2(*reinterpret_cast<__half2*>(&u3.x));
        float2 f3b = __half22float2(*reinterpret_cast<__half2*>(&u3.y));
        a.x = fmaf(f3a.x, n3, a.x); a.y = fmaf(f3a.y, n3, a.y);
        a.z = fmaf(f3b.x, n3, a.z); a.w = fmaf(f3b.y, n3, a.w);
    }
    for (; j < end; ++j) {
        int s0 = g_nbr[j];
        float n0 = dinv * g_deg[s0];
        uint2 u0 = *reinterpret_cast<const uint2*>(&g_h16[(size_t)s0 * FOUT + hl * 4]);
        float2 f0a = __half22float2(*reinterpret_cast<__half2*>(&u0.x));
        float2 f0b = __half22float2(*reinterpret_cast<__half2*>(&u0.y));
        a.x = fmaf(f0a.x, n0, a.x); a.y = fmaf(f0a.y, n0, a.y);
        a.z = fmaf(f0b.x, n0, a.z); a.w = fmaf(f0b.y, n0, a.w);
    }

    float4 bb = *reinterpret_cast<const float4*>(bias + hl * 4);
    a.x = fmaxf(a.x + bb.x, 0.f);
    a.y = fmaxf(a.y + bb.y, 0.f);
    a.z = fmaxf(a.z + bb.z, 0.f);
    a.w = fmaxf(a.w + bb.w, 0.f);
    *reinterpret_cast<float4*>(&out[(size_t)node * FOUT + hl * 4]) = a;
}

// ---------------------------------------------------------------------------
// Launch topology: unchanged fork/join (CSR build concurrent with GEMM).
extern "C" void kernel_launch(void* const* d_in, const int* in_sizes, int n_in,
                              void* d_out, int out_size)
{
    const float* x   = (const float*)d_in[0];   // [N, 256]
    const int*   adj = (const int*)d_in[1];     // [2, E]
    const float* W   = (const float*)d_in[2];   // [256, 64]
    const float* b   = (const float*)d_in[3];   // [64]
    float*       out = (float*)d_out;           // [N, 64]

    const int* src = adj;
    const int* dst = adj + EE;

    static cudaStream_t s2 = nullptr;
    static cudaEvent_t evF = nullptr, evJ = nullptr;
    if (!s2) {
        cudaStreamCreateWithFlags(&s2, cudaStreamNonBlocking);
        cudaEventCreateWithFlags(&evF, cudaEventDisableTiming);
        cudaEventCreateWithFlags(&evJ, cudaEventDisableTiming);
        cudaFuncSetAttribute(k_gemm_mma,
                             cudaFuncAttributeMaxDynamicSharedMemorySize, GEMM_SMEM);
    }

    // fork: s2 branch starts after the capture-stream front
    cudaEventRecord(evF, 0);
    cudaStreamWaitEvent(s2, evF, 0);

    // branch B (s2): CSR build chain
    k_zero<<<(NN + 255) / 256, 256, 0, s2>>>();
    k_count<<<(EE / 4 + 255) / 256, 256, 0, s2>>>(dst);
    k_scan_a<<<NBLK, 1024, 0, s2>>>();
    k_scan_c<<<NBLK, 1024, 0, s2>>>();
    k_fill<<<(EE / 4 + 255) / 256, 256, 0, s2>>>(src, dst);
    cudaEventRecord(evJ, s2);

    // branch A (main stream): GEMM, independent of CSR build
    k_gemm_mma<<<(NN + 127) / 128, 512, GEMM_SMEM>>>(x, W);

    // join: gather needs both branches
    cudaStreamWaitEvent(0, evJ, 0);
    k_gather<<<(NN / 2 + 7) / 8, 256>>>(b, out);
}